// round 9
// baseline (speedup 1.0000x reference)
#include <cuda_runtime.h>
#include <cuda_bf16.h>
#include <math.h>
#include <stdint.h>

#define BB 8
#define LL 2048
#define MM 2048
#define DD 256
#define OD 1024

#define LT 128      // CTA L rows
#define MT 32       // M tile
#define NTILES 64   // MM / MT

// ---------------------------------------------------------------------------
// Scratch (device globals)
// ---------------------------------------------------------------------------
__device__ float g_xs[BB*LL*DD];     // tf32-rounded input*dot_scale
__device__ float g_memr[BB*MM*DD];   // tf32-rounded memory
__device__ float g_indot[BB*LL], g_mbias[BB*MM];
__device__ float g_rowmax[BB*LL];
__device__ float g_gmax[BB], g_Z[BB], g_o2part[BB*32*DD];

// ---------------------------------------------------------------------------
// PTX helpers
// ---------------------------------------------------------------------------
__device__ __forceinline__ uint32_t smem_u32(const void* p) {
    uint32_t a;
    asm("{ .reg .u64 t; cvta.to.shared.u64 t, %1; cvt.u32.u64 %0, t; }" : "=r"(a) : "l"(p));
    return a;
}
__device__ __forceinline__ void ldsm_x4(uint32_t* r, uint32_t a) {
    asm volatile("ldmatrix.sync.aligned.m8n8.x4.shared.b16 {%0,%1,%2,%3}, [%4];"
        : "=r"(r[0]), "=r"(r[1]), "=r"(r[2]), "=r"(r[3]) : "r"(a));
}
__device__ __forceinline__ void mma_tf32(float* d, const uint32_t* a, uint32_t b0, uint32_t b1) {
    asm volatile("mma.sync.aligned.m16n8k8.row.col.f32.tf32.tf32.f32 "
        "{%0,%1,%2,%3}, {%4,%5,%6,%7}, {%8,%9}, {%0,%1,%2,%3};"
        : "+f"(d[0]), "+f"(d[1]), "+f"(d[2]), "+f"(d[3])
        : "r"(a[0]), "r"(a[1]), "r"(a[2]), "r"(a[3]), "r"(b0), "r"(b1));
}
__device__ __forceinline__ uint32_t tf32u(float x) {
    uint32_t r; asm("cvt.rna.tf32.f32 %0, %1;" : "=r"(r) : "f"(x)); return r;
}
__device__ __forceinline__ float tf32f(float x) { return __uint_as_float(tf32u(x)); }

__device__ __forceinline__ float fast_exp(float x) {
    x = fmaxf(x, -80.0f);
    float y = x * 1.4426950408889634f;
    float nf = y + 12582912.0f;
    int   i  = __float_as_int(nf);
    float n  = nf - 12582912.0f;
    float f  = y - n;
    float p = 1.5403530e-4f;
    p = fmaf(p, f, 1.3333558e-3f);
    p = fmaf(p, f, 9.6181291e-3f);
    p = fmaf(p, f, 5.5504109e-2f);
    p = fmaf(p, f, 2.4022651e-1f);
    p = fmaf(p, f, 6.9314718e-1f);
    p = fmaf(p, f, 1.0f);
    return p * __int_as_float((i - 0x4B3FFF81) << 23);
}
__device__ __forceinline__ void cp_async16(uint32_t dst, const void* src) {
    asm volatile("cp.async.cg.shared.global [%0], [%1], 16;" :: "r"(dst), "l"(src) : "memory");
}
__device__ __forceinline__ void cp_commit() {
    asm volatile("cp.async.commit_group;" ::: "memory");
}
template <int N>
__device__ __forceinline__ void cp_wait() {
    asm volatile("cp.async.wait_group %0;" :: "n"(N) : "memory");
}

// ---------------------------------------------------------------------------
// smem layout (bytes). fp32 tiles, row stride 268 floats (268 mod 32 = 12:
// conflict-free for b16-ldmatrix rows AND the PV LDS.32 pattern banks 12m+d).
// ---------------------------------------------------------------------------
#define SXF 268
#define SX_OFF  0                     // xs: 128 x 268 f32 = 137216
#define SMT_OFF 137216                // mem tiles: 2 x (32 x 268 f32 = 34304)
#define SMT_BUF 34304
#define SMB_OFF 205824                // mbias 2048 f32 = 8192
#define FUSED_SMEM 214016

// ---------------------------------------------------------------------------
// dots
// ---------------------------------------------------------------------------
__global__ void dots_kernel(const float* __restrict__ inp, const float* __restrict__ mem,
                            const float* __restrict__ mask, const float* __restrict__ wi,
                            const float* __restrict__ wm) {
    int row = blockIdx.x * 8 + (threadIdx.x >> 5);
    int lane = threadIdx.x & 31;
    bool isMem = row >= BB * LL;
    int r = isMem ? row - BB * LL : row;
    const float* src = (isMem ? mem : inp) + (size_t)r * DD;
    const float* w = isMem ? wm : wi;
    float s = 0.f;
    #pragma unroll
    for (int k = 0; k < 8; k++) { int d = lane + 32 * k; s = fmaf(src[d], w[d], s); }
    #pragma unroll
    for (int o = 16; o; o >>= 1) s += __shfl_xor_sync(0xffffffffu, s, o);
    if (lane == 0) {
        if (isMem) g_mbias[r] = s - 1e30f * (1.0f - mask[r]);
        else       g_indot[r] = s;
    }
}

// ---------------------------------------------------------------------------
// conv: tf32-round xs = input*ds and memory into fp32 scratch
// ---------------------------------------------------------------------------
__global__ void conv_kernel(const float* __restrict__ inp, const float* __restrict__ mem,
                            const float* __restrict__ ds) {
    const int N4 = BB * LL * DD / 4;
    int i = blockIdx.x * 256 + threadIdx.x;
    bool isMem = i >= N4;
    int j = isMem ? i - N4 : i;
    float4 x = ((const float4*)(isMem ? mem : inp))[j];
    if (!isMem) {
        float4 s = ((const float4*)ds)[j & (DD / 4 - 1)];
        x.x *= s.x; x.y *= s.y; x.z *= s.z; x.w *= s.w;
    }
    x.x = tf32f(x.x); x.y = tf32f(x.y); x.z = tf32f(x.z); x.w = tf32f(x.w);
    ((float4*)(isMem ? g_memr : g_xs))[j] = x;
}

// ---------------------------------------------------------------------------
// FUSED flash kernel, single-pass TF32. CTA = 128 L-rows, 64 M-tiles of 32.
// ---------------------------------------------------------------------------
__global__ void __launch_bounds__(256, 1) fused_kernel(const float* __restrict__ inp,
                                                       float* __restrict__ out) {
    extern __shared__ char sm[];
    const uint32_t s0 = smem_u32(sm);
    const int tid = threadIdx.x, lane = tid & 31, warp = tid >> 5;
    const int lbase = blockIdx.x * LT, b = blockIdx.y;

    // ---- async prologue ----
    // xs: 128 rows x 64 16B-chunks
    #pragma unroll
    for (int j = 0; j < 32; j++) {
        int i = tid + j * 256;
        int row = i >> 6, c = i & 63;
        size_t src = (size_t)(b * LL + lbase + row) * DD + c * 4;
        cp_async16(s0 + SX_OFF + (uint32_t)(row * SXF + c * 4) * 4, g_xs + src);
    }
    // mbias: 2048 f32 = 512 chunks
    #pragma unroll
    for (int j = 0; j < 2; j++) {
        int i = tid + j * 256;
        cp_async16(s0 + SMB_OFF + i * 16, g_mbias + b * MM + i * 4);
    }
    auto LOADMEM = [&](int t, int buf) {
        uint32_t base = s0 + SMT_OFF + (uint32_t)buf * SMT_BUF;
        #pragma unroll
        for (int j = 0; j < 8; j++) {
            int i = tid + j * 256;
            int row = i >> 6, c = i & 63;
            size_t src = (size_t)(b * MM + t * MT + row) * DD + c * 4;
            cp_async16(base + (uint32_t)(row * SXF + c * 4) * 4, g_memr + src);
        }
    };
    LOADMEM(0, 0);
    cp_commit();
    LOADMEM(1, 1);
    cp_commit();
    cp_wait<1>();
    __syncthreads();

    const int rr = lane >> 2, cc = (lane & 3) * 2;
    const int wl = warp * 16;
    const float idot0 = g_indot[b * LL + lbase + wl + rr];
    const float idot1 = g_indot[b * LL + lbase + wl + rr + 8];
    const float* smb = (const float*)(sm + SMB_OFF);

    // ldmatrix lane offsets (fp32-as-b16 trick; x4 tiles: T0 r0-7/c0-3, T1 r8-15/c0-3,
    // T2 r0-7/c4-7, T3 r8-15/c4-7 -> exactly the tf32 a0..a3 / b0-pairs layout)
    const uint32_t a_lane = (uint32_t)((wl + (lane & 7) + ((lane >> 3) & 1) * 8) * SXF) * 4
                          + (uint32_t)(lane >> 4) * 16;
    const uint32_t b_lane0 = (uint32_t)(((lane & 7) + ((lane >> 3) & 1) * 8) * SXF) * 4
                           + (uint32_t)(lane >> 4) * 16;
    const uint32_t b_lane1 = b_lane0 + (uint32_t)(16 * SXF) * 4;

    float O[32][4];
    #pragma unroll
    for (int nt = 0; nt < 32; nt++) { O[nt][0] = 0.f; O[nt][1] = 0.f; O[nt][2] = 0.f; O[nt][3] = 0.f; }
    float m0 = -INFINITY, m1 = -INFINITY, z0 = 0.f, z1 = 0.f;

    for (int t = 0; t < NTILES; t++) {
        const uint32_t mtb = s0 + SMT_OFF + (uint32_t)(t & 1) * SMT_BUF;

        // ---- S = xs . mem^T (single-pass tf32) ----
        float scf[4][4];
        #pragma unroll
        for (int nt = 0; nt < 4; nt++) { scf[nt][0]=0.f; scf[nt][1]=0.f; scf[nt][2]=0.f; scf[nt][3]=0.f; }
        #pragma unroll
        for (int ks = 0; ks < 32; ks++) {
            uint32_t ka[4], kb0[4], kb1[4];
            ldsm_x4(ka,  s0 + SX_OFF + a_lane + ks * 32);
            ldsm_x4(kb0, mtb + b_lane0 + ks * 32);
            ldsm_x4(kb1, mtb + b_lane1 + ks * 32);
            mma_tf32(scf[0], ka, kb0[0], kb0[2]);
            mma_tf32(scf[1], ka, kb0[1], kb0[3]);
            mma_tf32(scf[2], ka, kb1[0], kb1[2]);
            mma_tf32(scf[3], ka, kb1[1], kb1[3]);
        }

        // ---- bias + online softmax ----
        #pragma unroll
        for (int nt = 0; nt < 4; nt++) {
            int col = t * MT + nt * 8 + cc;
            float b0 = smb[col], b1 = smb[col + 1];
            scf[nt][0] += idot0 + b0; scf[nt][1] += idot0 + b1;
            scf[nt][2] += idot1 + b0; scf[nt][3] += idot1 + b1;
        }
        float tm0 = -INFINITY, tm1 = -INFINITY;
        #pragma unroll
        for (int nt = 0; nt < 4; nt++) {
            tm0 = fmaxf(tm0, fmaxf(scf[nt][0], scf[nt][1]));
            tm1 = fmaxf(tm1, fmaxf(scf[nt][2], scf[nt][3]));
        }
        #pragma unroll
        for (int x = 1; x <= 2; x <<= 1) {
            tm0 = fmaxf(tm0, __shfl_xor_sync(0xffffffffu, tm0, x));
            tm1 = fmaxf(tm1, __shfl_xor_sync(0xffffffffu, tm1, x));
        }
        float mn0 = fmaxf(m0, tm0), mn1 = fmaxf(m1, tm1);
        float sc0 = __expf(m0 - mn0), sc1 = __expf(m1 - mn1);
        m0 = mn0; m1 = mn1;
        float lz0 = 0.f, lz1 = 0.f;
        #pragma unroll
        for (int nt = 0; nt < 4; nt++) {
            scf[nt][0] = __expf(scf[nt][0] - m0);
            scf[nt][1] = __expf(scf[nt][1] - m0);
            scf[nt][2] = __expf(scf[nt][2] - m1);
            scf[nt][3] = __expf(scf[nt][3] - m1);
            lz0 += scf[nt][0] + scf[nt][1];
            lz1 += scf[nt][2] + scf[nt][3];
        }
        z0 = z0 * sc0 + lz0;
        z1 = z1 * sc1 + lz1;
        bool need = !__all_sync(0xffffffffu, (sc0 == 1.0f) && (sc1 == 1.0f));
        if (need) {
            #pragma unroll
            for (int nt = 0; nt < 32; nt++) {
                O[nt][0] *= sc0; O[nt][1] *= sc0;
                O[nt][2] *= sc1; O[nt][3] *= sc1;
            }
        }

        // ---- PV: O += P . mem (single-pass tf32) ----
        // Redistribute P (C-frag pair layout) into tf32 k8 A-frag layout via shuffles.
        const int sl0 = (lane & 0x1C) | ((lane & 3) >> 1);
        const int sl2 = sl0 | 2;
        const bool odd = lane & 1;
        #pragma unroll
        for (int ks = 0; ks < 4; ks++) {
            float v00 = __shfl_sync(0xffffffffu, scf[ks][0], sl0);
            float v01 = __shfl_sync(0xffffffffu, scf[ks][1], sl0);
            float v10 = __shfl_sync(0xffffffffu, scf[ks][2], sl0);
            float v11 = __shfl_sync(0xffffffffu, scf[ks][3], sl0);
            float v20 = __shfl_sync(0xffffffffu, scf[ks][0], sl2);
            float v21 = __shfl_sync(0xffffffffu, scf[ks][1], sl2);
            float v30 = __shfl_sync(0xffffffffu, scf[ks][2], sl2);
            float v31 = __shfl_sync(0xffffffffu, scf[ks][3], sl2);
            uint32_t pa[4];
            pa[0] = tf32u(odd ? v01 : v00);
            pa[1] = tf32u(odd ? v11 : v10);
            pa[2] = tf32u(odd ? v21 : v20);
            pa[3] = tf32u(odd ? v31 : v30);
            // B: trans access, conflict-free LDS.32 (banks 12m+d distinct)
            const float* br0 = (const float*)(sm + (mtb - s0))
                               + (ks * 8 + (lane & 3)) * SXF + (lane >> 2);
            const float* br1 = br0 + 4 * SXF;
            #pragma unroll
            for (int np = 0; np < 32; np++) {
                float bb0 = br0[np * 8], bb1 = br1[np * 8];
                mma_tf32(O[np], pa, __float_as_uint(bb0), __float_as_uint(bb1));
            }
        }

        __syncthreads();
        if (t + 2 < NTILES) LOADMEM(t + 2, t & 1);
        cp_commit();
        cp_wait<1>();
        __syncthreads();
    }

    // ---- epilogue ----
    #pragma unroll
    for (int x = 1; x <= 2; x <<= 1) {
        z0 += __shfl_xor_sync(0xffffffffu, z0, x);
        z1 += __shfl_xor_sync(0xffffffffu, z1, x);
    }
    float inv0 = 1.0f / z0, inv1 = 1.0f / z1;
    if ((lane & 3) == 0) {
        g_rowmax[b * LL + lbase + wl + rr] = m0;
        g_rowmax[b * LL + lbase + wl + rr + 8] = m1;
    }
    size_t grow0 = (size_t)(b * LL + lbase + wl + rr);
    size_t grow1 = grow0 + 8;
    float* ob0 = out + grow0 * OD;
    float* ob1 = out + grow1 * OD;
    const float* xi0 = inp + grow0 * DD;
    const float* xi1 = inp + grow1 * DD;
    #pragma unroll
    for (int nt = 0; nt < 32; nt++) {
        int d = nt * 8 + cc;
        float2 xv0 = *(const float2*)(xi0 + d);
        float2 xv1 = *(const float2*)(xi1 + d);
        float2 o0 = make_float2(O[nt][0] * inv0, O[nt][1] * inv0);
        float2 o1 = make_float2(O[nt][2] * inv1, O[nt][3] * inv1);
        *(float2*)(ob0 + d)          = xv0;
        *(float2*)(ob0 + DD + d)     = o0;
        *(float2*)(ob0 + 2 * DD + d) = make_float2(xv0.x * o0.x, xv0.y * o0.y);
        *(float2*)(ob1 + d)          = xv1;
        *(float2*)(ob1 + DD + d)     = o1;
        *(float2*)(ob1 + 2 * DD + d) = make_float2(xv1.x * o1.x, xv1.y * o1.y);
    }
}

// ---------------------------------------------------------------------------
// output_two path
// ---------------------------------------------------------------------------
__global__ void c0_kernel() {
    int b = blockIdx.x, tid = threadIdx.x;
    __shared__ float red[256];
    float m = -INFINITY;
    for (int l = tid; l < LL; l += 256) m = fmaxf(m, g_rowmax[b * LL + l]);
    red[tid] = m; __syncthreads();
    for (int s = 128; s; s >>= 1) { if (tid < s) red[tid] = fmaxf(red[tid], red[tid + s]); __syncthreads(); }
    float gmax = red[0]; __syncthreads();
    float z = 0.f;
    for (int l = tid; l < LL; l += 256) z += fast_exp(g_rowmax[b * LL + l] - gmax);
    red[tid] = z; __syncthreads();
    for (int s = 128; s; s >>= 1) { if (tid < s) red[tid] += red[tid + s]; __syncthreads(); }
    if (tid == 0) { g_gmax[b] = gmax; g_Z[b] = red[0]; }
}

__global__ void c1_kernel(const float* __restrict__ inp) {
    int b = blockIdx.y, sblk = blockIdx.x, tid = threadIdx.x;
    __shared__ float ws[64];
    int l0 = sblk * 64;
    if (tid < 64)
        ws[tid] = fast_exp(g_rowmax[b * LL + l0 + tid] - g_gmax[b]) * (1.0f / g_Z[b]);
    __syncthreads();
    float acc = 0.f;
    const float* xp = inp + ((size_t)b * LL + l0) * DD + tid;
    #pragma unroll 4
    for (int l = 0; l < 64; l++) acc = fmaf(ws[l], xp[(size_t)l * DD], acc);
    g_o2part[(b * 32 + sblk) * DD + tid] = acc;
}

__global__ void c2_kernel(float* __restrict__ out) {
    int b = blockIdx.y, tid = threadIdx.x;
    __shared__ float o2s[256];
    float a = 0.f;
    #pragma unroll
    for (int s = 0; s < 32; s++) a += g_o2part[(b * 32 + s) * DD + tid];
    o2s[tid] = a; __syncthreads();
    int lbase = blockIdx.x * 16;
    for (int rr = 0; rr < 16; rr++) {
        size_t ob = ((size_t)(b * LL + lbase + rr)) * OD;
        out[ob + 3 * DD + tid] = o2s[tid] * out[ob + DD + tid];
    }
}

// ---------------------------------------------------------------------------
extern "C" void kernel_launch(void* const* d_in, const int* in_sizes, int n_in,
                              void* d_out, int out_size) {
    const float* inp  = (const float*)d_in[0];
    const float* mem  = (const float*)d_in[1];
    const float* mask = (const float*)d_in[2];
    const float* wi   = (const float*)d_in[3];
    const float* wm   = (const float*)d_in[4];
    const float* ds   = (const float*)d_in[5];
    float* out = (float*)d_out;

    cudaFuncSetAttribute(fused_kernel, cudaFuncAttributeMaxDynamicSharedMemorySize, FUSED_SMEM);

    dots_kernel<<<(BB * (LL + MM)) / 8, 256>>>(inp, mem, mask, wi, wm);
    conv_kernel<<<2 * (BB * LL * DD / 4) / 256, 256>>>(inp, mem, ds);
    fused_kernel<<<dim3(LL / LT, BB), 256, FUSED_SMEM>>>(inp, out);
    c0_kernel<<<BB, 256>>>();
    c1_kernel<<<dim3(LL / 64, BB), 256>>>(inp);
    c2_kernel<<<dim3(LL / 16, BB), 256>>>(out);
}

// round 10
// speedup vs baseline: 1.3667x; 1.3667x over previous
#include <cuda_runtime.h>
#include <cuda_bf16.h>
#include <math.h>
#include <stdint.h>

#define BB 8
#define LL 2048
#define MM 2048
#define DD 256
#define OD 1024

#define LT 128      // CTA L rows
#define MT 32       // M tile
#define NTILES 64   // MM / MT

// ---------------------------------------------------------------------------
// Scratch (device globals)
// ---------------------------------------------------------------------------
__device__ __nv_bfloat16 g_xs_hi[BB*LL*DD],  g_xs_lo[BB*LL*DD];
__device__ __nv_bfloat16 g_mem_hi[BB*MM*DD], g_mem_lo[BB*MM*DD];
__device__ float g_indot[BB*LL], g_mbias[BB*MM];
__device__ float g_rowmax[BB*LL];
__device__ float g_gmax[BB], g_Z[BB], g_o2part[BB*32*DD];

// ---------------------------------------------------------------------------
// PTX helpers
// ---------------------------------------------------------------------------
__device__ __forceinline__ uint32_t smem_u32(const void* p) {
    uint32_t a;
    asm("{ .reg .u64 t; cvta.to.shared.u64 t, %1; cvt.u32.u64 %0, t; }" : "=r"(a) : "l"(p));
    return a;
}
__device__ __forceinline__ void ldsm_x4(uint32_t* r, uint32_t a) {
    asm volatile("ldmatrix.sync.aligned.m8n8.x4.shared.b16 {%0,%1,%2,%3}, [%4];"
        : "=r"(r[0]), "=r"(r[1]), "=r"(r[2]), "=r"(r[3]) : "r"(a));
}
__device__ __forceinline__ void ldsm_x2(uint32_t* r, uint32_t a) {
    asm volatile("ldmatrix.sync.aligned.m8n8.x2.shared.b16 {%0,%1}, [%2];"
        : "=r"(r[0]), "=r"(r[1]) : "r"(a));
}
__device__ __forceinline__ void ldsm_x2t(uint32_t* r, uint32_t a) {
    asm volatile("ldmatrix.sync.aligned.m8n8.x2.trans.shared.b16 {%0,%1}, [%2];"
        : "=r"(r[0]), "=r"(r[1]) : "r"(a));
}
__device__ __forceinline__ void mma16816(float* d, const uint32_t* a, const uint32_t* b) {
    asm volatile("mma.sync.aligned.m16n8k16.row.col.f32.bf16.bf16.f32 "
        "{%0,%1,%2,%3}, {%4,%5,%6,%7}, {%8,%9}, {%0,%1,%2,%3};"
        : "+f"(d[0]), "+f"(d[1]), "+f"(d[2]), "+f"(d[3])
        : "r"(a[0]), "r"(a[1]), "r"(a[2]), "r"(a[3]), "r"(b[0]), "r"(b[1]));
}
__device__ __forceinline__ void split4(float4 v, uint2& hi, uint2& lo) {
    __nv_bfloat16 h0 = __float2bfloat16(v.x), h1 = __float2bfloat16(v.y);
    __nv_bfloat16 h2 = __float2bfloat16(v.z), h3 = __float2bfloat16(v.w);
    __nv_bfloat16 l0 = __float2bfloat16(v.x - __bfloat162float(h0));
    __nv_bfloat16 l1 = __float2bfloat16(v.y - __bfloat162float(h1));
    __nv_bfloat16 l2 = __float2bfloat16(v.z - __bfloat162float(h2));
    __nv_bfloat16 l3 = __float2bfloat16(v.w - __bfloat162float(h3));
    hi.x = (uint32_t)__bfloat16_as_ushort(h0) | ((uint32_t)__bfloat16_as_ushort(h1) << 16);
    hi.y = (uint32_t)__bfloat16_as_ushort(h2) | ((uint32_t)__bfloat16_as_ushort(h3) << 16);
    lo.x = (uint32_t)__bfloat16_as_ushort(l0) | ((uint32_t)__bfloat16_as_ushort(l1) << 16);
    lo.y = (uint32_t)__bfloat16_as_ushort(l2) | ((uint32_t)__bfloat16_as_ushort(l3) << 16);
}
// pack two fp32 into bf16x2 (x -> low half, y -> high half), single CVT
__device__ __forceinline__ uint32_t pack2hi(float x, float y) {
    uint32_t r;
    asm("cvt.rn.bf16x2.f32 %0, %1, %2;" : "=r"(r) : "f"(y), "f"(x));
    return r;
}
__device__ __forceinline__ float fast_exp(float x) {
    x = fmaxf(x, -80.0f);
    float y = x * 1.4426950408889634f;
    float nf = y + 12582912.0f;
    int   i  = __float_as_int(nf);
    float n  = nf - 12582912.0f;
    float f  = y - n;
    float p = 1.5403530e-4f;
    p = fmaf(p, f, 1.3333558e-3f);
    p = fmaf(p, f, 9.6181291e-3f);
    p = fmaf(p, f, 5.5504109e-2f);
    p = fmaf(p, f, 2.4022651e-1f);
    p = fmaf(p, f, 6.9314718e-1f);
    p = fmaf(p, f, 1.0f);
    return p * __int_as_float((i - 0x4B3FFF81) << 23);
}
__device__ __forceinline__ void cp_async16(uint32_t dst, const void* src) {
    asm volatile("cp.async.cg.shared.global [%0], [%1], 16;" :: "r"(dst), "l"(src) : "memory");
}
__device__ __forceinline__ void cp_commit() {
    asm volatile("cp.async.commit_group;" ::: "memory");
}
template <int N>
__device__ __forceinline__ void cp_wait() {
    asm volatile("cp.async.wait_group %0;" :: "n"(N) : "memory");
}

// ---------------------------------------------------------------------------
// smem layout (bytes)
// ---------------------------------------------------------------------------
#define SXS 264                 // row stride in halves
#define SX_HI  0                // 128 x 264 halves = 67584
#define SX_LO  67584
#define SM_B   135168           // mem tiles: 2 bufs x (hi 16896 + lo 16896)
#define SM_BUF 33792
#define SM_LOO 16896
#define SMB    202752           // mbias 2048 f32 = 8192
#define FUSED_SMEM 210944

// ---------------------------------------------------------------------------
// dots
// ---------------------------------------------------------------------------
__global__ void dots_kernel(const float* __restrict__ inp, const float* __restrict__ mem,
                            const float* __restrict__ mask, const float* __restrict__ wi,
                            const float* __restrict__ wm) {
    int row = blockIdx.x * 8 + (threadIdx.x >> 5);
    int lane = threadIdx.x & 31;
    bool isMem = row >= BB * LL;
    int r = isMem ? row - BB * LL : row;
    const float* src = (isMem ? mem : inp) + (size_t)r * DD;
    const float* w = isMem ? wm : wi;
    float s = 0.f;
    #pragma unroll
    for (int k = 0; k < 8; k++) { int d = lane + 32 * k; s = fmaf(src[d], w[d], s); }
    #pragma unroll
    for (int o = 16; o; o >>= 1) s += __shfl_xor_sync(0xffffffffu, s, o);
    if (lane == 0) {
        if (isMem) g_mbias[r] = s - 1e30f * (1.0f - mask[r]);
        else       g_indot[r] = s;
    }
}

// ---------------------------------------------------------------------------
// conv: hi/lo bf16 split of xs = input*ds and memory
// ---------------------------------------------------------------------------
__global__ void conv_kernel(const float* __restrict__ inp, const float* __restrict__ mem,
                            const float* __restrict__ ds) {
    const int N4 = BB * LL * DD / 4;
    int i = blockIdx.x * 256 + threadIdx.x;
    bool isMem = i >= N4;
    int j = isMem ? i - N4 : i;
    float4 x = ((const float4*)(isMem ? mem : inp))[j];
    if (!isMem) {
        float4 s = ((const float4*)ds)[j & (DD / 4 - 1)];
        x.x *= s.x; x.y *= s.y; x.z *= s.z; x.w *= s.w;
    }
    uint2 hv, lv;
    split4(x, hv, lv);
    ((uint2*)(isMem ? g_mem_hi : g_xs_hi))[j] = hv;
    ((uint2*)(isMem ? g_mem_lo : g_xs_lo))[j] = lv;
}

// ---------------------------------------------------------------------------
// FUSED flash kernel. CTA = 128 L-rows, 64 M-tiles of 32.
// S: bf16x3 (full precision logits). PV: single-pass bf16 (P_hi x mem_hi).
// ---------------------------------------------------------------------------
__global__ void __launch_bounds__(256, 1) fused_kernel(const float* __restrict__ inp,
                                                       float* __restrict__ out) {
    extern __shared__ char sm[];
    const uint32_t s0 = smem_u32(sm);
    const int tid = threadIdx.x, lane = tid & 31, warp = tid >> 5;
    const int lbase = blockIdx.x * LT, b = blockIdx.y;

    // ---- async prologue ----
    #pragma unroll
    for (int j = 0; j < 16; j++) {
        int i = tid + j * 256;
        int row = i >> 5, c = i & 31;
        size_t src = (size_t)(b * LL + lbase + row) * DD + c * 8;
        uint32_t d = (uint32_t)(row * SXS + c * 8) * 2;
        cp_async16(s0 + SX_HI + d, g_xs_hi + src);
        cp_async16(s0 + SX_LO + d, g_xs_lo + src);
    }
    #pragma unroll
    for (int j = 0; j < 2; j++) {
        int i = tid + j * 256;
        cp_async16(s0 + SMB + i * 16, g_mbias + b * MM + i * 4);
    }
    auto LOADMEM = [&](int t, int buf) {
        uint32_t base = s0 + SM_B + (uint32_t)buf * SM_BUF;
        #pragma unroll
        for (int j = 0; j < 4; j++) {
            int i = tid + j * 256;
            int row = i >> 5, c = i & 31;
            size_t src = (size_t)(b * MM + t * MT + row) * DD + c * 8;
            uint32_t d = (uint32_t)(row * SXS + c * 8) * 2;
            cp_async16(base + d, g_mem_hi + src);
            cp_async16(base + SM_LOO + d, g_mem_lo + src);
        }
    };
    LOADMEM(0, 0);
    cp_commit();
    LOADMEM(1, 1);
    cp_commit();
    cp_wait<1>();
    __syncthreads();

    const int q = lane >> 3, lr = lane & 7, h = (lane >> 3) & 1;
    const int rr = lane >> 2, cc = (lane & 3) * 2;
    const int wl = warp * 16;
    const float idot0 = g_indot[b * LL + lbase + wl + rr];
    const float idot1 = g_indot[b * LL + lbase + wl + rr + 8];
    const float* smb = (const float*)(sm + SMB);

    float O[32][4];
    #pragma unroll
    for (int nt = 0; nt < 32; nt++) { O[nt][0] = 0.f; O[nt][1] = 0.f; O[nt][2] = 0.f; O[nt][3] = 0.f; }
    float m0 = -INFINITY, m1 = -INFINITY, z0 = 0.f, z1 = 0.f;

    for (int t = 0; t < NTILES; t++) {
        const uint32_t mh = s0 + SM_B + (uint32_t)(t & 1) * SM_BUF;
        const uint32_t mlo = mh + SM_LOO;

        // ---- S = xs . mem^T (3-pass bf16) ----
        float scf[4][4];
        #pragma unroll
        for (int nt = 0; nt < 4; nt++) { scf[nt][0]=0.f; scf[nt][1]=0.f; scf[nt][2]=0.f; scf[nt][3]=0.f; }
        #pragma unroll
        for (int ks = 0; ks < 16; ks++) {
            uint32_t ao = (uint32_t)((wl + (q & 1) * 8 + lr) * SXS + ks * 16 + (q >> 1) * 8) * 2;
            uint32_t ah[4], al[4];
            ldsm_x4(ah, s0 + SX_HI + ao);
            ldsm_x4(al, s0 + SX_LO + ao);
            uint32_t bh[4][2], bl[4][2];
            #pragma unroll
            for (int nt = 0; nt < 4; nt++) {
                uint32_t bo = (uint32_t)((nt * 8 + lr) * SXS + ks * 16 + h * 8) * 2;
                ldsm_x2(bh[nt], mh + bo);
                ldsm_x2(bl[nt], mlo + bo);
            }
            #pragma unroll
            for (int nt = 0; nt < 4; nt++) mma16816(scf[nt], ah, bh[nt]);
            #pragma unroll
            for (int nt = 0; nt < 4; nt++) mma16816(scf[nt], ah, bl[nt]);
            #pragma unroll
            for (int nt = 0; nt < 4; nt++) mma16816(scf[nt], al, bh[nt]);
        }

        // ---- bias + online softmax ----
        #pragma unroll
        for (int nt = 0; nt < 4; nt++) {
            int col = t * MT + nt * 8 + cc;
            float b0 = smb[col], b1 = smb[col + 1];
            scf[nt][0] += idot0 + b0; scf[nt][1] += idot0 + b1;
            scf[nt][2] += idot1 + b0; scf[nt][3] += idot1 + b1;
        }
        float tm0 = -INFINITY, tm1 = -INFINITY;
        #pragma unroll
        for (int nt = 0; nt < 4; nt++) {
            tm0 = fmaxf(tm0, fmaxf(scf[nt][0], scf[nt][1]));
            tm1 = fmaxf(tm1, fmaxf(scf[nt][2], scf[nt][3]));
        }
        #pragma unroll
        for (int x = 1; x <= 2; x <<= 1) {
            tm0 = fmaxf(tm0, __shfl_xor_sync(0xffffffffu, tm0, x));
            tm1 = fmaxf(tm1, __shfl_xor_sync(0xffffffffu, tm1, x));
        }
        float mn0 = fmaxf(m0, tm0), mn1 = fmaxf(m1, tm1);
        float sc0 = __expf(m0 - mn0), sc1 = __expf(m1 - mn1);
        m0 = mn0; m1 = mn1;
        float lz0 = 0.f, lz1 = 0.f;
        #pragma unroll
        for (int nt = 0; nt < 4; nt++) {
            scf[nt][0] = __expf(scf[nt][0] - m0);
            scf[nt][1] = __expf(scf[nt][1] - m0);
            scf[nt][2] = __expf(scf[nt][2] - m1);
            scf[nt][3] = __expf(scf[nt][3] - m1);
            lz0 += scf[nt][0] + scf[nt][1];
            lz1 += scf[nt][2] + scf[nt][3];
        }
        z0 = z0 * sc0 + lz0;
        z1 = z1 * sc1 + lz1;
        bool need = !__all_sync(0xffffffffu, (sc0 == 1.0f) && (sc1 == 1.0f));
        if (need) {
            #pragma unroll
            for (int nt = 0; nt < 32; nt++) {
                O[nt][0] *= sc0; O[nt][1] *= sc0;
                O[nt][2] *= sc1; O[nt][3] *= sc1;
            }
        }

        // ---- pack P (hi only) into A-fragments ----
        uint32_t ph[2][4];
        #pragma unroll
        for (int j2 = 0; j2 < 2; j2++) {
            ph[j2][0] = pack2hi(scf[2*j2][0],   scf[2*j2][1]);
            ph[j2][1] = pack2hi(scf[2*j2][2],   scf[2*j2][3]);
            ph[j2][2] = pack2hi(scf[2*j2+1][0], scf[2*j2+1][1]);
            ph[j2][3] = pack2hi(scf[2*j2+1][2], scf[2*j2+1][3]);
        }

        // ---- PV: O += P_hi . mem_hi (single pass) ----
        #pragma unroll
        for (int ks = 0; ks < 2; ks++) {
            #pragma unroll
            for (int nt = 0; nt < 32; nt++) {
                uint32_t bo = (uint32_t)((ks * 16 + h * 8 + lr) * SXS + nt * 8) * 2;
                uint32_t bh2[2];
                ldsm_x2t(bh2, mh + bo);
                mma16816(O[nt], ph[ks], bh2);
            }
        }

        __syncthreads();
        if (t + 2 < NTILES) LOADMEM(t + 2, t & 1);
        cp_commit();
        cp_wait<1>();
        __syncthreads();
    }

    // ---- epilogue ----
    #pragma unroll
    for (int x = 1; x <= 2; x <<= 1) {
        z0 += __shfl_xor_sync(0xffffffffu, z0, x);
        z1 += __shfl_xor_sync(0xffffffffu, z1, x);
    }
    float inv0 = 1.0f / z0, inv1 = 1.0f / z1;
    if ((lane & 3) == 0) {
        g_rowmax[b * LL + lbase + wl + rr] = m0;
        g_rowmax[b * LL + lbase + wl + rr + 8] = m1;
    }
    size_t grow0 = (size_t)(b * LL + lbase + wl + rr);
    size_t grow1 = grow0 + 8;
    float* ob0 = out + grow0 * OD;
    float* ob1 = out + grow1 * OD;
    const float* xi0 = inp + grow0 * DD;
    const float* xi1 = inp + grow1 * DD;
    #pragma unroll
    for (int nt = 0; nt < 32; nt++) {
        int d = nt * 8 + cc;
        float2 xv0 = *(const float2*)(xi0 + d);
        float2 xv1 = *(const float2*)(xi1 + d);
        float2 o0 = make_float2(O[nt][0] * inv0, O[nt][1] * inv0);
        float2 o1 = make_float2(O[nt][2] * inv1, O[nt][3] * inv1);
        *(float2*)(ob0 + d)          = xv0;
        *(float2*)(ob0 + DD + d)     = o0;
        *(float2*)(ob0 + 2 * DD + d) = make_float2(xv0.x * o0.x, xv0.y * o0.y);
        *(float2*)(ob1 + d)          = xv1;
        *(float2*)(ob1 + DD + d)     = o1;
        *(float2*)(ob1 + 2 * DD + d) = make_float2(xv1.x * o1.x, xv1.y * o1.y);
    }
}

// ---------------------------------------------------------------------------
// output_two path
// ---------------------------------------------------------------------------
__global__ void c0_kernel() {
    int b = blockIdx.x, tid = threadIdx.x;
    __shared__ float red[256];
    float m = -INFINITY;
    for (int l = tid; l < LL; l += 256) m = fmaxf(m, g_rowmax[b * LL + l]);
    red[tid] = m; __syncthreads();
    for (int s = 128; s; s >>= 1) { if (tid < s) red[tid] = fmaxf(red[tid], red[tid + s]); __syncthreads(); }
    float gmax = red[0]; __syncthreads();
    float z = 0.f;
    for (int l = tid; l < LL; l += 256) z += fast_exp(g_rowmax[b * LL + l] - gmax);
    red[tid] = z; __syncthreads();
    for (int s = 128; s; s >>= 1) { if (tid < s) red[tid] += red[tid + s]; __syncthreads(); }
    if (tid == 0) { g_gmax[b] = gmax; g_Z[b] = red[0]; }
}

__global__ void c1_kernel(const float* __restrict__ inp) {
    int b = blockIdx.y, sblk = blockIdx.x, tid = threadIdx.x;
    __shared__ float ws[64];
    int l0 = sblk * 64;
    if (tid < 64)
        ws[tid] = fast_exp(g_rowmax[b * LL + l0 + tid] - g_gmax[b]) * (1.0f / g_Z[b]);
    __syncthreads();
    float acc = 0.f;
    const float* xp = inp + ((size_t)b * LL + l0) * DD + tid;
    #pragma unroll 4
    for (int l = 0; l < 64; l++) acc = fmaf(ws[l], xp[(size_t)l * DD], acc);
    g_o2part[(b * 32 + sblk) * DD + tid] = acc;
}

__global__ void c2_kernel(float* __restrict__ out) {
    int b = blockIdx.y, tid = threadIdx.x;
    __shared__ float o2s[256];
    float a = 0.f;
    #pragma unroll
    for (int s = 0; s < 32; s++) a += g_o2part[(b * 32 + s) * DD + tid];
    o2s[tid] = a; __syncthreads();
    int lbase = blockIdx.x * 16;
    for (int rr = 0; rr < 16; rr++) {
        size_t ob = ((size_t)(b * LL + lbase + rr)) * OD;
        out[ob + 3 * DD + tid] = o2s[tid] * out[ob + DD + tid];
    }
}

// ---------------------------------------------------------------------------
extern "C" void kernel_launch(void* const* d_in, const int* in_sizes, int n_in,
                              void* d_out, int out_size) {
    const float* inp  = (const float*)d_in[0];
    const float* mem  = (const float*)d_in[1];
    const float* mask = (const float*)d_in[2];
    const float* wi   = (const float*)d_in[3];
    const float* wm   = (const float*)d_in[4];
    const float* ds   = (const float*)d_in[5];
    float* out = (float*)d_out;

    cudaFuncSetAttribute(fused_kernel, cudaFuncAttributeMaxDynamicSharedMemorySize, FUSED_SMEM);

    dots_kernel<<<(BB * (LL + MM)) / 8, 256>>>(inp, mem, mask, wi, wm);
    conv_kernel<<<2 * (BB * LL * DD / 4) / 256, 256>>>(inp, mem, ds);
    fused_kernel<<<dim3(LL / LT, BB), 256, FUSED_SMEM>>>(inp, out);
    c0_kernel<<<BB, 256>>>();
    c1_kernel<<<dim3(LL / 64, BB), 256>>>(inp);
    c2_kernel<<<dim3(LL / 16, BB), 256>>>(out);
}

// round 11
// speedup vs baseline: 1.8068x; 1.3219x over previous
#include <cuda_runtime.h>
#include <cuda_bf16.h>
#include <math.h>
#include <stdint.h>

#define BB 8
#define LL 2048
#define MM 2048
#define DD 256
#define OD 1024

#define LT 128      // CTA L rows
#define MT 32       // M tile
#define NTILES 64   // MM / MT

// ---------------------------------------------------------------------------
// Scratch (device globals)
// ---------------------------------------------------------------------------
__device__ __nv_bfloat16 g_xs_hi[BB*LL*DD],  g_xs_lo[BB*LL*DD];
__device__ __nv_bfloat16 g_mem_hi[BB*MM*DD];
__device__ float g_indot[BB*LL], g_mbias[BB*MM];
__device__ float g_rowmax[BB*LL];
__device__ float g_gmax[BB], g_Z[BB], g_o2part[BB*32*DD];

// ---------------------------------------------------------------------------
// PTX helpers
// ---------------------------------------------------------------------------
__device__ __forceinline__ uint32_t smem_u32(const void* p) {
    uint32_t a;
    asm("{ .reg .u64 t; cvta.to.shared.u64 t, %1; cvt.u32.u64 %0, t; }" : "=r"(a) : "l"(p));
    return a;
}
__device__ __forceinline__ void ldsm_x4(uint32_t* r, uint32_t a) {
    asm volatile("ldmatrix.sync.aligned.m8n8.x4.shared.b16 {%0,%1,%2,%3}, [%4];"
        : "=r"(r[0]), "=r"(r[1]), "=r"(r[2]), "=r"(r[3]) : "r"(a));
}
__device__ __forceinline__ void ldsm_x2(uint32_t* r, uint32_t a) {
    asm volatile("ldmatrix.sync.aligned.m8n8.x2.shared.b16 {%0,%1}, [%2];"
        : "=r"(r[0]), "=r"(r[1]) : "r"(a));
}
__device__ __forceinline__ void ldsm_x2t(uint32_t* r, uint32_t a) {
    asm volatile("ldmatrix.sync.aligned.m8n8.x2.trans.shared.b16 {%0,%1}, [%2];"
        : "=r"(r[0]), "=r"(r[1]) : "r"(a));
}
__device__ __forceinline__ void mma16816(float* d, const uint32_t* a, const uint32_t* b) {
    asm volatile("mma.sync.aligned.m16n8k16.row.col.f32.bf16.bf16.f32 "
        "{%0,%1,%2,%3}, {%4,%5,%6,%7}, {%8,%9}, {%0,%1,%2,%3};"
        : "+f"(d[0]), "+f"(d[1]), "+f"(d[2]), "+f"(d[3])
        : "r"(a[0]), "r"(a[1]), "r"(a[2]), "r"(a[3]), "r"(b[0]), "r"(b[1]));
}
__device__ __forceinline__ void split4(float4 v, uint2& hi, uint2& lo) {
    __nv_bfloat16 h0 = __float2bfloat16(v.x), h1 = __float2bfloat16(v.y);
    __nv_bfloat16 h2 = __float2bfloat16(v.z), h3 = __float2bfloat16(v.w);
    __nv_bfloat16 l0 = __float2bfloat16(v.x - __bfloat162float(h0));
    __nv_bfloat16 l1 = __float2bfloat16(v.y - __bfloat162float(h1));
    __nv_bfloat16 l2 = __float2bfloat16(v.z - __bfloat162float(h2));
    __nv_bfloat16 l3 = __float2bfloat16(v.w - __bfloat162float(h3));
    hi.x = (uint32_t)__bfloat16_as_ushort(h0) | ((uint32_t)__bfloat16_as_ushort(h1) << 16);
    hi.y = (uint32_t)__bfloat16_as_ushort(h2) | ((uint32_t)__bfloat16_as_ushort(h3) << 16);
    lo.x = (uint32_t)__bfloat16_as_ushort(l0) | ((uint32_t)__bfloat16_as_ushort(l1) << 16);
    lo.y = (uint32_t)__bfloat16_as_ushort(l2) | ((uint32_t)__bfloat16_as_ushort(l3) << 16);
}
// pack two fp32 into bf16x2 (x -> low half, y -> high half), single CVT
__device__ __forceinline__ uint32_t pack2hi(float x, float y) {
    uint32_t r;
    asm("cvt.rn.bf16x2.f32 %0, %1, %2;" : "=r"(r) : "f"(y), "f"(x));
    return r;
}
__device__ __forceinline__ float fast_exp(float x) {
    x = fmaxf(x, -80.0f);
    float y = x * 1.4426950408889634f;
    float nf = y + 12582912.0f;
    int   i  = __float_as_int(nf);
    float n  = nf - 12582912.0f;
    float f  = y - n;
    float p = 1.5403530e-4f;
    p = fmaf(p, f, 1.3333558e-3f);
    p = fmaf(p, f, 9.6181291e-3f);
    p = fmaf(p, f, 5.5504109e-2f);
    p = fmaf(p, f, 2.4022651e-1f);
    p = fmaf(p, f, 6.9314718e-1f);
    p = fmaf(p, f, 1.0f);
    return p * __int_as_float((i - 0x4B3FFF81) << 23);
}
__device__ __forceinline__ void cp_async16(uint32_t dst, const void* src) {
    asm volatile("cp.async.cg.shared.global [%0], [%1], 16;" :: "r"(dst), "l"(src) : "memory");
}
__device__ __forceinline__ void cp_commit() {
    asm volatile("cp.async.commit_group;" ::: "memory");
}
template <int N>
__device__ __forceinline__ void cp_wait() {
    asm volatile("cp.async.wait_group %0;" :: "n"(N) : "memory");
}

// ---------------------------------------------------------------------------
// smem layout (bytes)
// ---------------------------------------------------------------------------
#define SXS 264                 // row stride in halves
#define SX_HI  0                // 128 x 264 halves = 67584
#define SX_LO  67584
#define SM_B   135168           // mem tiles: 2 bufs x (hi only, 16896)
#define SM_BUF 16896
#define SMB    168960           // mbias 2048 f32 = 8192
#define FUSED_SMEM 177152

// ---------------------------------------------------------------------------
// dots
// ---------------------------------------------------------------------------
__global__ void dots_kernel(const float* __restrict__ inp, const float* __restrict__ mem,
                            const float* __restrict__ mask, const float* __restrict__ wi,
                            const float* __restrict__ wm) {
    int row = blockIdx.x * 8 + (threadIdx.x >> 5);
    int lane = threadIdx.x & 31;
    bool isMem = row >= BB * LL;
    int r = isMem ? row - BB * LL : row;
    const float* src = (isMem ? mem : inp) + (size_t)r * DD;
    const float* w = isMem ? wm : wi;
    float s = 0.f;
    #pragma unroll
    for (int k = 0; k < 8; k++) { int d = lane + 32 * k; s = fmaf(src[d], w[d], s); }
    #pragma unroll
    for (int o = 16; o; o >>= 1) s += __shfl_xor_sync(0xffffffffu, s, o);
    if (lane == 0) {
        if (isMem) g_mbias[r] = s - 1e30f * (1.0f - mask[r]);
        else       g_indot[r] = s;
    }
}

// ---------------------------------------------------------------------------
// conv: hi/lo bf16 split of xs = input*ds; hi-only of memory
// ---------------------------------------------------------------------------
__global__ void conv_kernel(const float* __restrict__ inp, const float* __restrict__ mem,
                            const float* __restrict__ ds) {
    const int N4 = BB * LL * DD / 4;
    int i = blockIdx.x * 256 + threadIdx.x;
    bool isMem = i >= N4;
    int j = isMem ? i - N4 : i;
    float4 x = ((const float4*)(isMem ? mem : inp))[j];
    if (!isMem) {
        float4 s = ((const float4*)ds)[j & (DD / 4 - 1)];
        x.x *= s.x; x.y *= s.y; x.z *= s.z; x.w *= s.w;
    }
    uint2 hv, lv;
    split4(x, hv, lv);
    if (isMem) {
        ((uint2*)g_mem_hi)[j] = hv;
    } else {
        ((uint2*)g_xs_hi)[j] = hv;
        ((uint2*)g_xs_lo)[j] = lv;
    }
}

// ---------------------------------------------------------------------------
// FUSED flash kernel. CTA = 128 L-rows, 64 M-tiles of 32.
// S: 2-pass bf16 (ah.bh + al.bh). PV: single-pass bf16 (P_hi x mem_hi).
// ---------------------------------------------------------------------------
__global__ void __launch_bounds__(256, 1) fused_kernel(const float* __restrict__ inp,
                                                       float* __restrict__ out) {
    extern __shared__ char sm[];
    const uint32_t s0 = smem_u32(sm);
    const int tid = threadIdx.x, lane = tid & 31, warp = tid >> 5;
    const int lbase = blockIdx.x * LT, b = blockIdx.y;

    // ---- async prologue ----
    #pragma unroll
    for (int j = 0; j < 16; j++) {
        int i = tid + j * 256;
        int row = i >> 5, c = i & 31;
        size_t src = (size_t)(b * LL + lbase + row) * DD + c * 8;
        uint32_t d = (uint32_t)(row * SXS + c * 8) * 2;
        cp_async16(s0 + SX_HI + d, g_xs_hi + src);
        cp_async16(s0 + SX_LO + d, g_xs_lo + src);
    }
    #pragma unroll
    for (int j = 0; j < 2; j++) {
        int i = tid + j * 256;
        cp_async16(s0 + SMB + i * 16, g_mbias + b * MM + i * 4);
    }
    auto LOADMEM = [&](int t, int buf) {
        uint32_t base = s0 + SM_B + (uint32_t)buf * SM_BUF;
        #pragma unroll
        for (int j = 0; j < 4; j++) {
            int i = tid + j * 256;
            int row = i >> 5, c = i & 31;
            size_t src = (size_t)(b * MM + t * MT + row) * DD + c * 8;
            cp_async16(base + (uint32_t)(row * SXS + c * 8) * 2, g_mem_hi + src);
        }
    };
    LOADMEM(0, 0);
    cp_commit();
    LOADMEM(1, 1);
    cp_commit();
    cp_wait<1>();
    __syncthreads();

    const int q = lane >> 3, lr = lane & 7, h = (lane >> 3) & 1;
    const int rr = lane >> 2, cc = (lane & 3) * 2;
    const int wl = warp * 16;
    const float idot0 = g_indot[b * LL + lbase + wl + rr];
    const float idot1 = g_indot[b * LL + lbase + wl + rr + 8];
    const float* smb = (const float*)(sm + SMB);

    float O[32][4];
    #pragma unroll
    for (int nt = 0; nt < 32; nt++) { O[nt][0] = 0.f; O[nt][1] = 0.f; O[nt][2] = 0.f; O[nt][3] = 0.f; }
    float m0 = -INFINITY, m1 = -INFINITY, z0 = 0.f, z1 = 0.f;

    for (int t = 0; t < NTILES; t++) {
        const uint32_t mh = s0 + SM_B + (uint32_t)(t & 1) * SM_BUF;

        // ---- S = xs . mem^T (2-pass bf16: ah.bh + al.bh) ----
        float scf[4][4];
        #pragma unroll
        for (int nt = 0; nt < 4; nt++) { scf[nt][0]=0.f; scf[nt][1]=0.f; scf[nt][2]=0.f; scf[nt][3]=0.f; }
        #pragma unroll
        for (int ks = 0; ks < 16; ks++) {
            uint32_t ao = (uint32_t)((wl + (q & 1) * 8 + lr) * SXS + ks * 16 + (q >> 1) * 8) * 2;
            uint32_t ah[4], al[4];
            ldsm_x4(ah, s0 + SX_HI + ao);
            ldsm_x4(al, s0 + SX_LO + ao);
            uint32_t bh[4][2];
            #pragma unroll
            for (int nt = 0; nt < 4; nt++) {
                uint32_t bo = (uint32_t)((nt * 8 + lr) * SXS + ks * 16 + h * 8) * 2;
                ldsm_x2(bh[nt], mh + bo);
            }
            #pragma unroll
            for (int nt = 0; nt < 4; nt++) mma16816(scf[nt], ah, bh[nt]);
            #pragma unroll
            for (int nt = 0; nt < 4; nt++) mma16816(scf[nt], al, bh[nt]);
        }

        // ---- bias + online softmax ----
        #pragma unroll
        for (int nt = 0; nt < 4; nt++) {
            int col = t * MT + nt * 8 + cc;
            float b0 = smb[col], b1 = smb[col + 1];
            scf[nt][0] += idot0 + b0; scf[nt][1] += idot0 + b1;
            scf[nt][2] += idot1 + b0; scf[nt][3] += idot1 + b1;
        }
        float tm0 = -INFINITY, tm1 = -INFINITY;
        #pragma unroll
        for (int nt = 0; nt < 4; nt++) {
            tm0 = fmaxf(tm0, fmaxf(scf[nt][0], scf[nt][1]));
            tm1 = fmaxf(tm1, fmaxf(scf[nt][2], scf[nt][3]));
        }
        #pragma unroll
        for (int x = 1; x <= 2; x <<= 1) {
            tm0 = fmaxf(tm0, __shfl_xor_sync(0xffffffffu, tm0, x));
            tm1 = fmaxf(tm1, __shfl_xor_sync(0xffffffffu, tm1, x));
        }
        float mn0 = fmaxf(m0, tm0), mn1 = fmaxf(m1, tm1);
        float sc0 = __expf(m0 - mn0), sc1 = __expf(m1 - mn1);
        m0 = mn0; m1 = mn1;
        float lz0 = 0.f, lz1 = 0.f;
        #pragma unroll
        for (int nt = 0; nt < 4; nt++) {
            scf[nt][0] = __expf(scf[nt][0] - m0);
            scf[nt][1] = __expf(scf[nt][1] - m0);
            scf[nt][2] = __expf(scf[nt][2] - m1);
            scf[nt][3] = __expf(scf[nt][3] - m1);
            lz0 += scf[nt][0] + scf[nt][1];
            lz1 += scf[nt][2] + scf[nt][3];
        }
        z0 = z0 * sc0 + lz0;
        z1 = z1 * sc1 + lz1;
        bool need = !__all_sync(0xffffffffu, (sc0 == 1.0f) && (sc1 == 1.0f));
        if (need) {
            #pragma unroll
            for (int nt = 0; nt < 32; nt++) {
                O[nt][0] *= sc0; O[nt][1] *= sc0;
                O[nt][2] *= sc1; O[nt][3] *= sc1;
            }
        }

        // ---- pack P (hi only) into A-fragments ----
        uint32_t ph[2][4];
        #pragma unroll
        for (int j2 = 0; j2 < 2; j2++) {
            ph[j2][0] = pack2hi(scf[2*j2][0],   scf[2*j2][1]);
            ph[j2][1] = pack2hi(scf[2*j2][2],   scf[2*j2][3]);
            ph[j2][2] = pack2hi(scf[2*j2+1][0], scf[2*j2+1][1]);
            ph[j2][3] = pack2hi(scf[2*j2+1][2], scf[2*j2+1][3]);
        }

        // ---- PV: O += P_hi . mem_hi (single pass) ----
        #pragma unroll
        for (int ks = 0; ks < 2; ks++) {
            #pragma unroll
            for (int nt = 0; nt < 32; nt++) {
                uint32_t bo = (uint32_t)((ks * 16 + h * 8 + lr) * SXS + nt * 8) * 2;
                uint32_t bh2[2];
                ldsm_x2t(bh2, mh + bo);
                mma16816(O[nt], ph[ks], bh2);
            }
        }

        __syncthreads();
        if (t + 2 < NTILES) LOADMEM(t + 2, t & 1);
        cp_commit();
        cp_wait<1>();
        __syncthreads();
    }

    // ---- epilogue ----
    #pragma unroll
    for (int x = 1; x <= 2; x <<= 1) {
        z0 += __shfl_xor_sync(0xffffffffu, z0, x);
        z1 += __shfl_xor_sync(0xffffffffu, z1, x);
    }
    float inv0 = 1.0f / z0, inv1 = 1.0f / z1;
    if ((lane & 3) == 0) {
        g_rowmax[b * LL + lbase + wl + rr] = m0;
        g_rowmax[b * LL + lbase + wl + rr + 8] = m1;
    }
    size_t grow0 = (size_t)(b * LL + lbase + wl + rr);
    size_t grow1 = grow0 + 8;
    float* ob0 = out + grow0 * OD;
    float* ob1 = out + grow1 * OD;
    const float* xi0 = inp + grow0 * DD;
    const float* xi1 = inp + grow1 * DD;
    #pragma unroll
    for (int nt = 0; nt < 32; nt++) {
        int d = nt * 8 + cc;
        float2 xv0 = *(const float2*)(xi0 + d);
        float2 xv1 = *(const float2*)(xi1 + d);
        float2 o0 = make_float2(O[nt][0] * inv0, O[nt][1] * inv0);
        float2 o1 = make_float2(O[nt][2] * inv1, O[nt][3] * inv1);
        *(float2*)(ob0 + d)          = xv0;
        *(float2*)(ob0 + DD + d)     = o0;
        *(float2*)(ob0 + 2 * DD + d) = make_float2(xv0.x * o0.x, xv0.y * o0.y);
        *(float2*)(ob1 + d)          = xv1;
        *(float2*)(ob1 + DD + d)     = o1;
        *(float2*)(ob1 + 2 * DD + d) = make_float2(xv1.x * o1.x, xv1.y * o1.y);
    }
}

// ---------------------------------------------------------------------------
// output_two path
// ---------------------------------------------------------------------------
__global__ void c0_kernel() {
    int b = blockIdx.x, tid = threadIdx.x;
    __shared__ float red[256];
    float m = -INFINITY;
    for (int l = tid; l < LL; l += 256) m = fmaxf(m, g_rowmax[b * LL + l]);
    red[tid] = m; __syncthreads();
    for (int s = 128; s; s >>= 1) { if (tid < s) red[tid] = fmaxf(red[tid], red[tid + s]); __syncthreads(); }
    float gmax = red[0]; __syncthreads();
    float z = 0.f;
    for (int l = tid; l < LL; l += 256) z += fast_exp(g_rowmax[b * LL + l] - gmax);
    red[tid] = z; __syncthreads();
    for (int s = 128; s; s >>= 1) { if (tid < s) red[tid] += red[tid + s]; __syncthreads(); }
    if (tid == 0) { g_gmax[b] = gmax; g_Z[b] = red[0]; }
}

__global__ void c1_kernel(const float* __restrict__ inp) {
    int b = blockIdx.y, sblk = blockIdx.x, tid = threadIdx.x;
    __shared__ float ws[64];
    int l0 = sblk * 64;
    if (tid < 64)
        ws[tid] = fast_exp(g_rowmax[b * LL + l0 + tid] - g_gmax[b]) * (1.0f / g_Z[b]);
    __syncthreads();
    float acc = 0.f;
    const float* xp = inp + ((size_t)b * LL + l0) * DD + tid;
    #pragma unroll 4
    for (int l = 0; l < 64; l++) acc = fmaf(ws[l], xp[(size_t)l * DD], acc);
    g_o2part[(b * 32 + sblk) * DD + tid] = acc;
}

__global__ void c2_kernel(float* __restrict__ out) {
    int b = blockIdx.y, tid = threadIdx.x;
    __shared__ float o2s[256];
    float a = 0.f;
    #pragma unroll
    for (int s = 0; s < 32; s++) a += g_o2part[(b * 32 + s) * DD + tid];
    o2s[tid] = a; __syncthreads();
    int lbase = blockIdx.x * 16;
    for (int rr = 0; rr < 16; rr++) {
        size_t ob = ((size_t)(b * LL + lbase + rr)) * OD;
        out[ob + 3 * DD + tid] = o2s[tid] * out[ob + DD + tid];
    }
}

// ---------------------------------------------------------------------------
extern "C" void kernel_launch(void* const* d_in, const int* in_sizes, int n_in,
                              void* d_out, int out_size) {
    const float* inp  = (const float*)d_in[0];
    const float* mem  = (const float*)d_in[1];
    const float* mask = (const float*)d_in[2];
    const float* wi   = (const float*)d_in[3];
    const float* wm   = (const float*)d_in[4];
    const float* ds   = (const float*)d_in[5];
    float* out = (float*)d_out;

    cudaFuncSetAttribute(fused_kernel, cudaFuncAttributeMaxDynamicSharedMemorySize, FUSED_SMEM);

    dots_kernel<<<(BB * (LL + MM)) / 8, 256>>>(inp, mem, mask, wi, wm);
    conv_kernel<<<2 * (BB * LL * DD / 4) / 256, 256>>>(inp, mem, ds);
    fused_kernel<<<dim3(LL / LT, BB), 256, FUSED_SMEM>>>(inp, out);
    c0_kernel<<<BB, 256>>>();
    c1_kernel<<<dim3(LL / 64, BB), 256>>>(inp);
    c2_kernel<<<dim3(LL / 16, BB), 256>>>(out);
}

// round 12
// speedup vs baseline: 1.8074x; 1.0003x over previous
#include <cuda_runtime.h>
#include <cuda_bf16.h>
#include <math.h>
#include <stdint.h>

#define BB 8
#define LL 2048
#define MM 2048
#define DD 256
#define OD 1024

#define LT 128      // CTA L rows
#define MT 32       // M tile
#define NTILES 64   // MM / MT

// ---------------------------------------------------------------------------
// Scratch (device globals)
// ---------------------------------------------------------------------------
__device__ __nv_bfloat16 g_xs_hi[BB*LL*DD],  g_xs_lo[BB*LL*DD];
__device__ __nv_bfloat16 g_mem_hi[BB*MM*DD];
__device__ float g_indot[BB*LL], g_mbias[BB*MM];
__device__ float g_rowmax[BB*LL];
__device__ float g_gmax[BB], g_Z[BB], g_o2part[BB*32*DD];

// ---------------------------------------------------------------------------
// PTX helpers
// ---------------------------------------------------------------------------
__device__ __forceinline__ uint32_t smem_u32(const void* p) {
    uint32_t a;
    asm("{ .reg .u64 t; cvta.to.shared.u64 t, %1; cvt.u32.u64 %0, t; }" : "=r"(a) : "l"(p));
    return a;
}
__device__ __forceinline__ void ldsm_x4(uint32_t* r, uint32_t a) {
    asm volatile("ldmatrix.sync.aligned.m8n8.x4.shared.b16 {%0,%1,%2,%3}, [%4];"
        : "=r"(r[0]), "=r"(r[1]), "=r"(r[2]), "=r"(r[3]) : "r"(a));
}
__device__ __forceinline__ void ldsm_x4t(uint32_t* r, uint32_t a) {
    asm volatile("ldmatrix.sync.aligned.m8n8.x4.trans.shared.b16 {%0,%1,%2,%3}, [%4];"
        : "=r"(r[0]), "=r"(r[1]), "=r"(r[2]), "=r"(r[3]) : "r"(a));
}
__device__ __forceinline__ void mma16816(float* d, const uint32_t* a, const uint32_t* b) {
    asm volatile("mma.sync.aligned.m16n8k16.row.col.f32.bf16.bf16.f32 "
        "{%0,%1,%2,%3}, {%4,%5,%6,%7}, {%8,%9}, {%0,%1,%2,%3};"
        : "+f"(d[0]), "+f"(d[1]), "+f"(d[2]), "+f"(d[3])
        : "r"(a[0]), "r"(a[1]), "r"(a[2]), "r"(a[3]), "r"(b[0]), "r"(b[1]));
}
__device__ __forceinline__ void split4(float4 v, uint2& hi, uint2& lo) {
    __nv_bfloat16 h0 = __float2bfloat16(v.x), h1 = __float2bfloat16(v.y);
    __nv_bfloat16 h2 = __float2bfloat16(v.z), h3 = __float2bfloat16(v.w);
    __nv_bfloat16 l0 = __float2bfloat16(v.x - __bfloat162float(h0));
    __nv_bfloat16 l1 = __float2bfloat16(v.y - __bfloat162float(h1));
    __nv_bfloat16 l2 = __float2bfloat16(v.z - __bfloat162float(h2));
    __nv_bfloat16 l3 = __float2bfloat16(v.w - __bfloat162float(h3));
    hi.x = (uint32_t)__bfloat16_as_ushort(h0) | ((uint32_t)__bfloat16_as_ushort(h1) << 16);
    hi.y = (uint32_t)__bfloat16_as_ushort(h2) | ((uint32_t)__bfloat16_as_ushort(h3) << 16);
    lo.x = (uint32_t)__bfloat16_as_ushort(l0) | ((uint32_t)__bfloat16_as_ushort(l1) << 16);
    lo.y = (uint32_t)__bfloat16_as_ushort(l2) | ((uint32_t)__bfloat16_as_ushort(l3) << 16);
}
// pack two fp32 into bf16x2 (x -> low half, y -> high half), single CVT
__device__ __forceinline__ uint32_t pack2hi(float x, float y) {
    uint32_t r;
    asm("cvt.rn.bf16x2.f32 %0, %1, %2;" : "=r"(r) : "f"(y), "f"(x));
    return r;
}
__device__ __forceinline__ float fast_exp(float x) {
    x = fmaxf(x, -80.0f);
    float y = x * 1.4426950408889634f;
    float nf = y + 12582912.0f;
    int   i  = __float_as_int(nf);
    float n  = nf - 12582912.0f;
    float f  = y - n;
    float p = 1.5403530e-4f;
    p = fmaf(p, f, 1.3333558e-3f);
    p = fmaf(p, f, 9.6181291e-3f);
    p = fmaf(p, f, 5.5504109e-2f);
    p = fmaf(p, f, 2.4022651e-1f);
    p = fmaf(p, f, 6.9314718e-1f);
    p = fmaf(p, f, 1.0f);
    return p * __int_as_float((i - 0x4B3FFF81) << 23);
}
__device__ __forceinline__ void cp_async16(uint32_t dst, const void* src) {
    asm volatile("cp.async.cg.shared.global [%0], [%1], 16;" :: "r"(dst), "l"(src) : "memory");
}
__device__ __forceinline__ void cp_commit() {
    asm volatile("cp.async.commit_group;" ::: "memory");
}
template <int N>
__device__ __forceinline__ void cp_wait() {
    asm volatile("cp.async.wait_group %0;" :: "n"(N) : "memory");
}

// ---------------------------------------------------------------------------
// smem layout (bytes)
// ---------------------------------------------------------------------------
#define SXS 264                 // row stride in halves
#define SX_HI  0                // 128 x 264 halves = 67584
#define SX_LO  67584
#define SM_B   135168           // mem tiles: 2 bufs x (hi only, 16896)
#define SM_BUF 16896
#define SMB    168960           // mbias 2048 f32 = 8192
#define FUSED_SMEM 177152

// ---------------------------------------------------------------------------
// prep: fused dots + hi/lo split (one pass over input & memory)
// warp per row; 8 warps per block.
// ---------------------------------------------------------------------------
__global__ void prep_kernel(const float* __restrict__ inp, const float* __restrict__ mem,
                            const float* __restrict__ mask, const float* __restrict__ wi,
                            const float* __restrict__ wm, const float* __restrict__ ds) {
    int row = blockIdx.x * 8 + (threadIdx.x >> 5);
    int lane = threadIdx.x & 31;
    bool isMem = row >= BB * LL;
    int r = isMem ? row - BB * LL : row;
    const float4* src = (const float4*)((isMem ? mem : inp) + (size_t)r * DD);
    const float4* w4  = (const float4*)(isMem ? wm : wi);
    const float4* ds4 = (const float4*)ds;

    float4 v0 = src[lane * 2], v1 = src[lane * 2 + 1];
    float4 w0 = w4[lane * 2],  w1 = w4[lane * 2 + 1];
    float s = v0.x * w0.x + v0.y * w0.y + v0.z * w0.z + v0.w * w0.w
            + v1.x * w1.x + v1.y * w1.y + v1.z * w1.z + v1.w * w1.w;
    #pragma unroll
    for (int o = 16; o; o >>= 1) s += __shfl_xor_sync(0xffffffffu, s, o);

    if (isMem) {
        if (lane == 0) g_mbias[r] = s - 1e30f * (1.0f - mask[r]);
        uint2 hv, lv;
        size_t j = (size_t)r * (DD / 4) + lane * 2;
        split4(v0, hv, lv); ((uint2*)g_mem_hi)[j] = hv;
        split4(v1, hv, lv); ((uint2*)g_mem_hi)[j + 1] = hv;
    } else {
        if (lane == 0) g_indot[r] = s;
        float4 d0 = ds4[lane * 2], d1 = ds4[lane * 2 + 1];
        v0.x *= d0.x; v0.y *= d0.y; v0.z *= d0.z; v0.w *= d0.w;
        v1.x *= d1.x; v1.y *= d1.y; v1.z *= d1.z; v1.w *= d1.w;
        uint2 hv, lv;
        size_t j = (size_t)r * (DD / 4) + lane * 2;
        split4(v0, hv, lv);
        ((uint2*)g_xs_hi)[j] = hv; ((uint2*)g_xs_lo)[j] = lv;
        split4(v1, hv, lv);
        ((uint2*)g_xs_hi)[j + 1] = hv; ((uint2*)g_xs_lo)[j + 1] = lv;
    }
}

// ---------------------------------------------------------------------------
// FUSED flash kernel. CTA = 128 L-rows, 64 M-tiles of 32.
// S: 2-pass bf16 (ah.bh + al.bh), x4 ldsm. PV: 1-pass bf16, x4t ldsm.
// ---------------------------------------------------------------------------
__global__ void __launch_bounds__(256, 1) fused_kernel(const float* __restrict__ inp,
                                                       float* __restrict__ out) {
    extern __shared__ char sm[];
    const uint32_t s0 = smem_u32(sm);
    const int tid = threadIdx.x, lane = tid & 31, warp = tid >> 5;
    const int lbase = blockIdx.x * LT, b = blockIdx.y;

    // ---- async prologue ----
    #pragma unroll
    for (int j = 0; j < 16; j++) {
        int i = tid + j * 256;
        int row = i >> 5, c = i & 31;
        size_t src = (size_t)(b * LL + lbase + row) * DD + c * 8;
        uint32_t d = (uint32_t)(row * SXS + c * 8) * 2;
        cp_async16(s0 + SX_HI + d, g_xs_hi + src);
        cp_async16(s0 + SX_LO + d, g_xs_lo + src);
    }
    #pragma unroll
    for (int j = 0; j < 2; j++) {
        int i = tid + j * 256;
        cp_async16(s0 + SMB + i * 16, g_mbias + b * MM + i * 4);
    }
    auto LOADMEM = [&](int t, int buf) {
        uint32_t base = s0 + SM_B + (uint32_t)buf * SM_BUF;
        #pragma unroll
        for (int j = 0; j < 4; j++) {
            int i = tid + j * 256;
            int row = i >> 5, c = i & 31;
            size_t src = (size_t)(b * MM + t * MT + row) * DD + c * 8;
            cp_async16(base + (uint32_t)(row * SXS + c * 8) * 2, g_mem_hi + src);
        }
    };
    LOADMEM(0, 0);
    cp_commit();
    LOADMEM(1, 1);
    cp_commit();
    cp_wait<1>();
    __syncthreads();

    const int q = lane >> 3, lr = lane & 7;
    const int rr = lane >> 2, cc = (lane & 3) * 2;
    const int wl = warp * 16;
    const float idot0 = g_indot[b * LL + lbase + wl + rr];
    const float idot1 = g_indot[b * LL + lbase + wl + rr + 8];
    const float* smb = (const float*)(sm + SMB);

    float O[32][4];
    #pragma unroll
    for (int nt = 0; nt < 32; nt++) { O[nt][0] = 0.f; O[nt][1] = 0.f; O[nt][2] = 0.f; O[nt][3] = 0.f; }
    float m0 = -INFINITY, m1 = -INFINITY, z0 = 0.f, z1 = 0.f;

    for (int t = 0; t < NTILES; t++) {
        const uint32_t mh = s0 + SM_B + (uint32_t)(t & 1) * SM_BUF;

        // ---- S = xs . mem^T (2-pass bf16: ah.bh + al.bh), x4 B-ldsm ----
        float scf[4][4];
        #pragma unroll
        for (int nt = 0; nt < 4; nt++) { scf[nt][0]=0.f; scf[nt][1]=0.f; scf[nt][2]=0.f; scf[nt][3]=0.f; }
        #pragma unroll
        for (int ks = 0; ks < 16; ks++) {
            uint32_t ao = (uint32_t)((wl + (q & 1) * 8 + lr) * SXS + ks * 16 + (q >> 1) * 8) * 2;
            uint32_t ah[4], al[4];
            ldsm_x4(ah, s0 + SX_HI + ao);
            ldsm_x4(al, s0 + SX_LO + ao);
            // B x4 non-trans: bh0 -> n-tiles 0,1 ; bh1 -> n-tiles 2,3
            uint32_t bh0[4], bh1[4];
            uint32_t bo0 = (uint32_t)(((q >> 1) * 8 + lr) * SXS + ks * 16 + (q & 1) * 8) * 2;
            uint32_t bo1 = bo0 + (uint32_t)(16 * SXS) * 2;
            ldsm_x4(bh0, mh + bo0);
            ldsm_x4(bh1, mh + bo1);
            mma16816(scf[0], ah, bh0);     mma16816(scf[1], ah, bh0 + 2);
            mma16816(scf[2], ah, bh1);     mma16816(scf[3], ah, bh1 + 2);
            mma16816(scf[0], al, bh0);     mma16816(scf[1], al, bh0 + 2);
            mma16816(scf[2], al, bh1);     mma16816(scf[3], al, bh1 + 2);
        }

        // ---- bias + online softmax ----
        #pragma unroll
        for (int nt = 0; nt < 4; nt++) {
            int col = t * MT + nt * 8 + cc;
            float b0 = smb[col], b1 = smb[col + 1];
            scf[nt][0] += idot0 + b0; scf[nt][1] += idot0 + b1;
            scf[nt][2] += idot1 + b0; scf[nt][3] += idot1 + b1;
        }
        float tm0 = -INFINITY, tm1 = -INFINITY;
        #pragma unroll
        for (int nt = 0; nt < 4; nt++) {
            tm0 = fmaxf(tm0, fmaxf(scf[nt][0], scf[nt][1]));
            tm1 = fmaxf(tm1, fmaxf(scf[nt][2], scf[nt][3]));
        }
        #pragma unroll
        for (int x = 1; x <= 2; x <<= 1) {
            tm0 = fmaxf(tm0, __shfl_xor_sync(0xffffffffu, tm0, x));
            tm1 = fmaxf(tm1, __shfl_xor_sync(0xffffffffu, tm1, x));
        }
        float mn0 = fmaxf(m0, tm0), mn1 = fmaxf(m1, tm1);
        float sc0 = __expf(m0 - mn0), sc1 = __expf(m1 - mn1);
        m0 = mn0; m1 = mn1;
        float lz0 = 0.f, lz1 = 0.f;
        #pragma unroll
        for (int nt = 0; nt < 4; nt++) {
            scf[nt][0] = __expf(scf[nt][0] - m0);
            scf[nt][1] = __expf(scf[nt][1] - m0);
            scf[nt][2] = __expf(scf[nt][2] - m1);
            scf[nt][3] = __expf(scf[nt][3] - m1);
            lz0 += scf[nt][0] + scf[nt][1];
            lz1 += scf[nt][2] + scf[nt][3];
        }
        z0 = z0 * sc0 + lz0;
        z1 = z1 * sc1 + lz1;
        bool need = !__all_sync(0xffffffffu, (sc0 == 1.0f) && (sc1 == 1.0f));
        if (need) {
            #pragma unroll
            for (int nt = 0; nt < 32; nt++) {
                O[nt][0] *= sc0; O[nt][1] *= sc0;
                O[nt][2] *= sc1; O[nt][3] *= sc1;
            }
        }

        // ---- pack P (hi only) into A-fragments ----
        uint32_t ph[2][4];
        #pragma unroll
        for (int j2 = 0; j2 < 2; j2++) {
            ph[j2][0] = pack2hi(scf[2*j2][0],   scf[2*j2][1]);
            ph[j2][1] = pack2hi(scf[2*j2][2],   scf[2*j2][3]);
            ph[j2][2] = pack2hi(scf[2*j2+1][0], scf[2*j2+1][1]);
            ph[j2][3] = pack2hi(scf[2*j2+1][2], scf[2*j2+1][3]);
        }

        // ---- PV: O += P_hi . mem_hi (single pass), x4t B-ldsm ----
        #pragma unroll
        for (int ks = 0; ks < 2; ks++) {
            #pragma unroll
            for (int np = 0; np < 16; np++) {
                uint32_t bo = (uint32_t)((ks * 16 + (q & 1) * 8 + lr) * SXS + np * 16 + (q >> 1) * 8) * 2;
                uint32_t bh4[4];
                ldsm_x4t(bh4, mh + bo);
                mma16816(O[2*np],   ph[ks], bh4);
                mma16816(O[2*np+1], ph[ks], bh4 + 2);
            }
        }

        __syncthreads();
        if (t + 2 < NTILES) LOADMEM(t + 2, t & 1);
        cp_commit();
        cp_wait<1>();
        __syncthreads();
    }

    // ---- epilogue ----
    #pragma unroll
    for (int x = 1; x <= 2; x <<= 1) {
        z0 += __shfl_xor_sync(0xffffffffu, z0, x);
        z1 += __shfl_xor_sync(0xffffffffu, z1, x);
    }
    float inv0 = 1.0f / z0, inv1 = 1.0f / z1;
    if ((lane & 3) == 0) {
        g_rowmax[b * LL + lbase + wl + rr] = m0;
        g_rowmax[b * LL + lbase + wl + rr + 8] = m1;
    }
    size_t grow0 = (size_t)(b * LL + lbase + wl + rr);
    size_t grow1 = grow0 + 8;
    float* ob0 = out + grow0 * OD;
    float* ob1 = out + grow1 * OD;
    const float* xi0 = inp + grow0 * DD;
    const float* xi1 = inp + grow1 * DD;
    #pragma unroll
    for (int nt = 0; nt < 32; nt++) {
        int d = nt * 8 + cc;
        float2 xv0 = *(const float2*)(xi0 + d);
        float2 xv1 = *(const float2*)(xi1 + d);
        float2 o0 = make_float2(O[nt][0] * inv0, O[nt][1] * inv0);
        float2 o1 = make_float2(O[nt][2] * inv1, O[nt][3] * inv1);
        *(float2*)(ob0 + d)          = xv0;
        *(float2*)(ob0 + DD + d)     = o0;
        *(float2*)(ob0 + 2 * DD + d) = make_float2(xv0.x * o0.x, xv0.y * o0.y);
        *(float2*)(ob1 + d)          = xv1;
        *(float2*)(ob1 + DD + d)     = o1;
        *(float2*)(ob1 + 2 * DD + d) = make_float2(xv1.x * o1.x, xv1.y * o1.y);
    }
}

// ---------------------------------------------------------------------------
// output_two path
// ---------------------------------------------------------------------------
__global__ void c0_kernel() {
    int b = blockIdx.x, tid = threadIdx.x;
    __shared__ float red[256];
    float m = -INFINITY;
    for (int l = tid; l < LL; l += 256) m = fmaxf(m, g_rowmax[b * LL + l]);
    red[tid] = m; __syncthreads();
    for (int s = 128; s; s >>= 1) { if (tid < s) red[tid] = fmaxf(red[tid], red[tid + s]); __syncthreads(); }
    float gmax = red[0]; __syncthreads();
    float z = 0.f;
    for (int l = tid; l < LL; l += 256) z += fast_exp(g_rowmax[b * LL + l] - gmax);
    red[tid] = z; __syncthreads();
    for (int s = 128; s; s >>= 1) { if (tid < s) red[tid] += red[tid + s]; __syncthreads(); }
    if (tid == 0) { g_gmax[b] = gmax; g_Z[b] = red[0]; }
}

__global__ void c1_kernel(const float* __restrict__ inp) {
    int b = blockIdx.y, sblk = blockIdx.x, tid = threadIdx.x;
    __shared__ float ws[64];
    int l0 = sblk * 64;
    if (tid < 64)
        ws[tid] = fast_exp(g_rowmax[b * LL + l0 + tid] - g_gmax[b]) * (1.0f / g_Z[b]);
    __syncthreads();
    float acc = 0.f;
    const float* xp = inp + ((size_t)b * LL + l0) * DD + tid;
    #pragma unroll 4
    for (int l = 0; l < 64; l++) acc = fmaf(ws[l], xp[(size_t)l * DD], acc);
    g_o2part[(b * 32 + sblk) * DD + tid] = acc;
}

__global__ void c2_kernel(float* __restrict__ out) {
    int b = blockIdx.y, tid = threadIdx.x;
    __shared__ float o2s[256];
    float a = 0.f;
    #pragma unroll
    for (int s = 0; s < 32; s++) a += g_o2part[(b * 32 + s) * DD + tid];
    o2s[tid] = a; __syncthreads();
    int lbase = blockIdx.x * 16;
    for (int rr = 0; rr < 16; rr++) {
        size_t ob = ((size_t)(b * LL + lbase + rr)) * OD;
        out[ob + 3 * DD + tid] = o2s[tid] * out[ob + DD + tid];
    }
}

// ---------------------------------------------------------------------------
extern "C" void kernel_launch(void* const* d_in, const int* in_sizes, int n_in,
                              void* d_out, int out_size) {
    const float* inp  = (const float*)d_in[0];
    const float* mem  = (const float*)d_in[1];
    const float* mask = (const float*)d_in[2];
    const float* wi   = (const float*)d_in[3];
    const float* wm   = (const float*)d_in[4];
    const float* ds   = (const float*)d_in[5];
    float* out = (float*)d_out;

    cudaFuncSetAttribute(fused_kernel, cudaFuncAttributeMaxDynamicSharedMemorySize, FUSED_SMEM);

    prep_kernel<<<(BB * (LL + MM)) / 8, 256>>>(inp, mem, mask, wi, wm, ds);
    fused_kernel<<<dim3(LL / LT, BB), 256, FUSED_SMEM>>>(inp, out);
    c0_kernel<<<BB, 256>>>();
    c1_kernel<<<dim3(LL / 64, BB), 256>>>(inp);
    c2_kernel<<<dim3(LL / 16, BB), 256>>>(out);
}

// round 13
// speedup vs baseline: 1.8657x; 1.0323x over previous
#include <cuda_runtime.h>
#include <cuda_bf16.h>
#include <math.h>
#include <stdint.h>

#define BB 8
#define LL 2048
#define MM 2048
#define DD 256
#define OD 1024

#define LT 128      // CTA L rows
#define MT 32       // M tile
#define NTILES 64   // MM / MT

// ---------------------------------------------------------------------------
// Scratch (device globals)
// ---------------------------------------------------------------------------
__device__ __nv_bfloat16 g_xs_hi[BB*LL*DD],  g_xs_lo[BB*LL*DD];
__device__ __nv_bfloat16 g_mem_hi[BB*MM*DD];
__device__ float g_indot[BB*LL], g_mbias[BB*MM];
__device__ float g_rowmax[BB*LL];
__device__ float g_o2part[BB*32*DD];

// ---------------------------------------------------------------------------
// PTX helpers
// ---------------------------------------------------------------------------
__device__ __forceinline__ uint32_t smem_u32(const void* p) {
    uint32_t a;
    asm("{ .reg .u64 t; cvta.to.shared.u64 t, %1; cvt.u32.u64 %0, t; }" : "=r"(a) : "l"(p));
    return a;
}
__device__ __forceinline__ void ldsm_x4(uint32_t* r, uint32_t a) {
    asm volatile("ldmatrix.sync.aligned.m8n8.x4.shared.b16 {%0,%1,%2,%3}, [%4];"
        : "=r"(r[0]), "=r"(r[1]), "=r"(r[2]), "=r"(r[3]) : "r"(a));
}
__device__ __forceinline__ void ldsm_x4t(uint32_t* r, uint32_t a) {
    asm volatile("ldmatrix.sync.aligned.m8n8.x4.trans.shared.b16 {%0,%1,%2,%3}, [%4];"
        : "=r"(r[0]), "=r"(r[1]), "=r"(r[2]), "=r"(r[3]) : "r"(a));
}
__device__ __forceinline__ void mma16816(float* d, const uint32_t* a, const uint32_t* b) {
    asm volatile("mma.sync.aligned.m16n8k16.row.col.f32.bf16.bf16.f32 "
        "{%0,%1,%2,%3}, {%4,%5,%6,%7}, {%8,%9}, {%0,%1,%2,%3};"
        : "+f"(d[0]), "+f"(d[1]), "+f"(d[2]), "+f"(d[3])
        : "r"(a[0]), "r"(a[1]), "r"(a[2]), "r"(a[3]), "r"(b[0]), "r"(b[1]));
}
__device__ __forceinline__ void split4(float4 v, uint2& hi, uint2& lo) {
    __nv_bfloat16 h0 = __float2bfloat16(v.x), h1 = __float2bfloat16(v.y);
    __nv_bfloat16 h2 = __float2bfloat16(v.z), h3 = __float2bfloat16(v.w);
    __nv_bfloat16 l0 = __float2bfloat16(v.x - __bfloat162float(h0));
    __nv_bfloat16 l1 = __float2bfloat16(v.y - __bfloat162float(h1));
    __nv_bfloat16 l2 = __float2bfloat16(v.z - __bfloat162float(h2));
    __nv_bfloat16 l3 = __float2bfloat16(v.w - __bfloat162float(h3));
    hi.x = (uint32_t)__bfloat16_as_ushort(h0) | ((uint32_t)__bfloat16_as_ushort(h1) << 16);
    hi.y = (uint32_t)__bfloat16_as_ushort(h2) | ((uint32_t)__bfloat16_as_ushort(h3) << 16);
    lo.x = (uint32_t)__bfloat16_as_ushort(l0) | ((uint32_t)__bfloat16_as_ushort(l1) << 16);
    lo.y = (uint32_t)__bfloat16_as_ushort(l2) | ((uint32_t)__bfloat16_as_ushort(l3) << 16);
}
__device__ __forceinline__ uint32_t pack2hi(float x, float y) {
    uint32_t r;
    asm("cvt.rn.bf16x2.f32 %0, %1, %2;" : "=r"(r) : "f"(y), "f"(x));
    return r;
}
__device__ __forceinline__ float fast_exp(float x) {
    x = fmaxf(x, -80.0f);
    float y = x * 1.4426950408889634f;
    float nf = y + 12582912.0f;
    int   i  = __float_as_int(nf);
    float n  = nf - 12582912.0f;
    float f  = y - n;
    float p = 1.5403530e-4f;
    p = fmaf(p, f, 1.3333558e-3f);
    p = fmaf(p, f, 9.6181291e-3f);
    p = fmaf(p, f, 5.5504109e-2f);
    p = fmaf(p, f, 2.4022651e-1f);
    p = fmaf(p, f, 6.9314718e-1f);
    p = fmaf(p, f, 1.0f);
    return p * __int_as_float((i - 0x4B3FFF81) << 23);
}
__device__ __forceinline__ void cp_async16(uint32_t dst, const void* src) {
    asm volatile("cp.async.cg.shared.global [%0], [%1], 16;" :: "r"(dst), "l"(src) : "memory");
}
__device__ __forceinline__ void cp_commit() {
    asm volatile("cp.async.commit_group;" ::: "memory");
}
template <int N>
__device__ __forceinline__ void cp_wait() {
    asm volatile("cp.async.wait_group %0;" :: "n"(N) : "memory");
}

// ---------------------------------------------------------------------------
// smem layout (bytes): 4-deep mem-tile ring
// ---------------------------------------------------------------------------
#define SXS 264                 // row stride in halves
#define SX_HI  0                // 128 x 264 halves = 67584
#define SX_LO  67584
#define SM_B   135168           // mem tiles: 4 bufs x 16896 = 67584
#define SM_BUF 16896
#define SMB    202752           // mbias 2048 f32 = 8192
#define FUSED_SMEM 210944

// ---------------------------------------------------------------------------
// prep: fused dots + hi/lo split
// ---------------------------------------------------------------------------
__global__ void prep_kernel(const float* __restrict__ inp, const float* __restrict__ mem,
                            const float* __restrict__ mask, const float* __restrict__ wi,
                            const float* __restrict__ wm, const float* __restrict__ ds) {
    int row = blockIdx.x * 8 + (threadIdx.x >> 5);
    int lane = threadIdx.x & 31;
    bool isMem = row >= BB * LL;
    int r = isMem ? row - BB * LL : row;
    const float4* src = (const float4*)((isMem ? mem : inp) + (size_t)r * DD);
    const float4* w4  = (const float4*)(isMem ? wm : wi);
    const float4* ds4 = (const float4*)ds;

    float4 v0 = src[lane * 2], v1 = src[lane * 2 + 1];
    float4 w0 = w4[lane * 2],  w1 = w4[lane * 2 + 1];
    float s = v0.x * w0.x + v0.y * w0.y + v0.z * w0.z + v0.w * w0.w
            + v1.x * w1.x + v1.y * w1.y + v1.z * w1.z + v1.w * w1.w;
    #pragma unroll
    for (int o = 16; o; o >>= 1) s += __shfl_xor_sync(0xffffffffu, s, o);

    if (isMem) {
        if (lane == 0) g_mbias[r] = s - 1e30f * (1.0f - mask[r]);
        uint2 hv, lv;
        size_t j = (size_t)r * (DD / 4) + lane * 2;
        split4(v0, hv, lv); ((uint2*)g_mem_hi)[j] = hv;
        split4(v1, hv, lv); ((uint2*)g_mem_hi)[j + 1] = hv;
    } else {
        if (lane == 0) g_indot[r] = s;
        float4 d0 = ds4[lane * 2], d1 = ds4[lane * 2 + 1];
        v0.x *= d0.x; v0.y *= d0.y; v0.z *= d0.z; v0.w *= d0.w;
        v1.x *= d1.x; v1.y *= d1.y; v1.z *= d1.z; v1.w *= d1.w;
        uint2 hv, lv;
        size_t j = (size_t)r * (DD / 4) + lane * 2;
        split4(v0, hv, lv);
        ((uint2*)g_xs_hi)[j] = hv; ((uint2*)g_xs_lo)[j] = lv;
        split4(v1, hv, lv);
        ((uint2*)g_xs_hi)[j + 1] = hv; ((uint2*)g_xs_lo)[j + 1] = lv;
    }
}

// ---------------------------------------------------------------------------
// FUSED flash kernel, deferred-PV pipeline.
// iter t: [one cp_wait+sync] softmax(t) ; burst{ S(t+1) + PV(t-1) } ; rescale(t)
// ---------------------------------------------------------------------------
__global__ void __launch_bounds__(256, 1) fused_kernel(const float* __restrict__ inp,
                                                       float* __restrict__ out) {
    extern __shared__ char sm[];
    const uint32_t s0 = smem_u32(sm);
    const int tid = threadIdx.x, lane = tid & 31, warp = tid >> 5;
    const int lbase = blockIdx.x * LT, b = blockIdx.y;

    // ---- async prologue ----
    #pragma unroll
    for (int j = 0; j < 16; j++) {
        int i = tid + j * 256;
        int row = i >> 5, c = i & 31;
        size_t src = (size_t)(b * LL + lbase + row) * DD + c * 8;
        uint32_t d = (uint32_t)(row * SXS + c * 8) * 2;
        cp_async16(s0 + SX_HI + d, g_xs_hi + src);
        cp_async16(s0 + SX_LO + d, g_xs_lo + src);
    }
    #pragma unroll
    for (int j = 0; j < 2; j++) {
        int i = tid + j * 256;
        cp_async16(s0 + SMB + i * 16, g_mbias + b * MM + i * 4);
    }
    auto LOADMEM = [&](int t, int buf) {
        uint32_t base = s0 + SM_B + (uint32_t)buf * SM_BUF;
        #pragma unroll
        for (int j = 0; j < 4; j++) {
            int i = tid + j * 256;
            int row = i >> 5, c = i & 31;
            size_t src = (size_t)(b * MM + t * MT + row) * DD + c * 8;
            cp_async16(base + (uint32_t)(row * SXS + c * 8) * 2, g_mem_hi + src);
        }
    };
    LOADMEM(0, 0);
    cp_commit();               // G0: xs + mbias + buf0
    LOADMEM(1, 1);
    cp_commit();               // G1: buf1
    cp_wait<1>();
    __syncthreads();           // xs, mbias, buf0 visible

    const int q = lane >> 3, lr = lane & 7;
    const int rr = lane >> 2, cc = (lane & 3) * 2;
    const int wl = warp * 16;
    const float idot0 = g_indot[b * LL + lbase + wl + rr];
    const float idot1 = g_indot[b * LL + lbase + wl + rr + 8];
    const float* smb = (const float*)(sm + SMB);

    float O[32][4];
    #pragma unroll
    for (int nt = 0; nt < 32; nt++) { O[nt][0] = 0.f; O[nt][1] = 0.f; O[nt][2] = 0.f; O[nt][3] = 0.f; }
    float m0 = -INFINITY, m1 = -INFINITY, z0 = 0.f, z1 = 0.f;

    float scf0[4][4], scf1[4][4];
    uint32_t ph0[2][4], ph1[2][4];

    // S-burst macro: computes S(tile) from buf MH into SCFN (zero-init inside)
    #define SBURST(MH, SCFN)                                                          \
    {                                                                                 \
        _Pragma("unroll")                                                             \
        for (int nt = 0; nt < 4; nt++) {                                              \
            SCFN[nt][0] = 0.f; SCFN[nt][1] = 0.f; SCFN[nt][2] = 0.f; SCFN[nt][3] = 0.f; \
        }                                                                             \
        _Pragma("unroll")                                                             \
        for (int ks = 0; ks < 16; ks++) {                                             \
            uint32_t ao = (uint32_t)((wl + (q & 1) * 8 + lr) * SXS + ks * 16 + (q >> 1) * 8) * 2; \
            uint32_t ah[4], al[4];                                                    \
            ldsm_x4(ah, s0 + SX_HI + ao);                                             \
            ldsm_x4(al, s0 + SX_LO + ao);                                             \
            uint32_t bh0[4], bh1[4];                                                  \
            uint32_t bo0 = (uint32_t)(((q >> 1) * 8 + lr) * SXS + ks * 16 + (q & 1) * 8) * 2; \
            uint32_t bo1 = bo0 + (uint32_t)(16 * SXS) * 2;                            \
            ldsm_x4(bh0, (MH) + bo0);                                                 \
            ldsm_x4(bh1, (MH) + bo1);                                                 \
            mma16816(SCFN[0], ah, bh0); mma16816(SCFN[1], ah, bh0 + 2);               \
            mma16816(SCFN[2], ah, bh1); mma16816(SCFN[3], ah, bh1 + 2);               \
            mma16816(SCFN[0], al, bh0); mma16816(SCFN[1], al, bh0 + 2);               \
            mma16816(SCFN[2], al, bh1); mma16816(SCFN[3], al, bh1 + 2);               \
        }                                                                             \
    }

    // PV-burst macro: O += P(PH) . mem(buf MH)
    #define PVBURST(MH, PH)                                                           \
    {                                                                                 \
        _Pragma("unroll")                                                             \
        for (int ks2 = 0; ks2 < 2; ks2++) {                                           \
            _Pragma("unroll")                                                         \
            for (int np = 0; np < 16; np++) {                                         \
                uint32_t bo = (uint32_t)((ks2 * 16 + (q & 1) * 8 + lr) * SXS + np * 16 + (q >> 1) * 8) * 2; \
                uint32_t bh4[4];                                                      \
                ldsm_x4t(bh4, (MH) + bo);                                             \
                mma16816(O[2*np],   PH[ks2], bh4);                                    \
                mma16816(O[2*np+1], PH[ks2], bh4 + 2);                                \
            }                                                                         \
        }                                                                             \
    }

    // one pipeline iteration
    #define ITER(T, SCFC, SCFN, PHN, PHO, DOS, DOPV)                                  \
    {                                                                                 \
        cp_wait<0>();                                                                 \
        __syncthreads();                                                              \
        if ((T) + 2 < NTILES) LOADMEM((T) + 2, ((T) + 2) & 3);                        \
        cp_commit();                                                                  \
        /* softmax(T) on SCFC */                                                      \
        _Pragma("unroll")                                                             \
        for (int nt = 0; nt < 4; nt++) {                                              \
            int col = (T) * MT + nt * 8 + cc;                                         \
            float b0_ = smb[col], b1_ = smb[col + 1];                                 \
            SCFC[nt][0] += idot0 + b0_; SCFC[nt][1] += idot0 + b1_;                   \
            SCFC[nt][2] += idot1 + b0_; SCFC[nt][3] += idot1 + b1_;                   \
        }                                                                             \
        float tm0 = -INFINITY, tm1 = -INFINITY;                                       \
        _Pragma("unroll")                                                             \
        for (int nt = 0; nt < 4; nt++) {                                              \
            tm0 = fmaxf(tm0, fmaxf(SCFC[nt][0], SCFC[nt][1]));                        \
            tm1 = fmaxf(tm1, fmaxf(SCFC[nt][2], SCFC[nt][3]));                        \
        }                                                                             \
        _Pragma("unroll")                                                             \
        for (int x = 1; x <= 2; x <<= 1) {                                            \
            tm0 = fmaxf(tm0, __shfl_xor_sync(0xffffffffu, tm0, x));                   \
            tm1 = fmaxf(tm1, __shfl_xor_sync(0xffffffffu, tm1, x));                   \
        }                                                                             \
        float mn0 = fmaxf(m0, tm0), mn1 = fmaxf(m1, tm1);                             \
        float sc0 = __expf(m0 - mn0), sc1 = __expf(m1 - mn1);                         \
        m0 = mn0; m1 = mn1;                                                           \
        float lz0 = 0.f, lz1 = 0.f;                                                   \
        _Pragma("unroll")                                                             \
        for (int nt = 0; nt < 4; nt++) {                                              \
            SCFC[nt][0] = __expf(SCFC[nt][0] - m0);                                   \
            SCFC[nt][1] = __expf(SCFC[nt][1] - m0);                                   \
            SCFC[nt][2] = __expf(SCFC[nt][2] - m1);                                   \
            SCFC[nt][3] = __expf(SCFC[nt][3] - m1);                                   \
            lz0 += SCFC[nt][0] + SCFC[nt][1];                                         \
            lz1 += SCFC[nt][2] + SCFC[nt][3];                                         \
        }                                                                             \
        z0 = z0 * sc0 + lz0;                                                          \
        z1 = z1 * sc1 + lz1;                                                          \
        _Pragma("unroll")                                                             \
        for (int j2 = 0; j2 < 2; j2++) {                                              \
            PHN[j2][0] = pack2hi(SCFC[2*j2][0],   SCFC[2*j2][1]);                     \
            PHN[j2][1] = pack2hi(SCFC[2*j2][2],   SCFC[2*j2][3]);                     \
            PHN[j2][2] = pack2hi(SCFC[2*j2+1][0], SCFC[2*j2+1][1]);                   \
            PHN[j2][3] = pack2hi(SCFC[2*j2+1][2], SCFC[2*j2+1][3]);                   \
        }                                                                             \
        /* merged MMA burst: S(T+1) + PV(T-1) */                                      \
        const uint32_t mhS = s0 + SM_B + (uint32_t)(((T) + 1) & 3) * SM_BUF;          \
        const uint32_t mhP = s0 + SM_B + (uint32_t)(((T) - 1) & 3) * SM_BUF;          \
        if (DOS) SBURST(mhS, SCFN);                                                   \
        if (DOPV) PVBURST(mhP, PHO);                                                  \
        /* rescale O (after PV(T-1) accumulated) */                                   \
        bool need = !__all_sync(0xffffffffu, (sc0 == 1.0f) && (sc1 == 1.0f));         \
        if (need) {                                                                   \
            _Pragma("unroll")                                                         \
            for (int nt = 0; nt < 32; nt++) {                                         \
                O[nt][0] *= sc0; O[nt][1] *= sc0;                                     \
                O[nt][2] *= sc1; O[nt][3] *= sc1;                                     \
            }                                                                         \
        }                                                                             \
    }

    // prologue burst: S(0) from buf0
    {
        const uint32_t mh0 = s0 + SM_B;
        SBURST(mh0, scf0);
    }

    // iter 0: softmax(0), S(1), no PV
    ITER(0, scf0, scf1, ph0, ph1, true, false);
    // iters 1..62 (pairs)
    for (int t = 1; t < 63; t += 2) {
        ITER(t,     scf1, scf0, ph1, ph0, true, true);
        ITER(t + 1, scf0, scf1, ph0, ph1, true, true);
    }
    // iter 63: softmax(63), PV(62), no S
    ITER(63, scf1, scf0, ph1, ph0, false, true);
    // final PV(63) from buf 63&3 = 3
    {
        const uint32_t mhF = s0 + SM_B + (uint32_t)(63 & 3) * SM_BUF;
        PVBURST(mhF, ph1);
    }

    // ---- epilogue ----
    #pragma unroll
    for (int x = 1; x <= 2; x <<= 1) {
        z0 += __shfl_xor_sync(0xffffffffu, z0, x);
        z1 += __shfl_xor_sync(0xffffffffu, z1, x);
    }
    float inv0 = 1.0f / z0, inv1 = 1.0f / z1;
    if ((lane & 3) == 0) {
        g_rowmax[b * LL + lbase + wl + rr] = m0;
        g_rowmax[b * LL + lbase + wl + rr + 8] = m1;
    }
    size_t grow0 = (size_t)(b * LL + lbase + wl + rr);
    size_t grow1 = grow0 + 8;
    float* ob0 = out + grow0 * OD;
    float* ob1 = out + grow1 * OD;
    const float* xi0 = inp + grow0 * DD;
    const float* xi1 = inp + grow1 * DD;
    #pragma unroll
    for (int nt = 0; nt < 32; nt++) {
        int d = nt * 8 + cc;
        float2 xv0 = *(const float2*)(xi0 + d);
        float2 xv1 = *(const float2*)(xi1 + d);
        float2 o0 = make_float2(O[nt][0] * inv0, O[nt][1] * inv0);
        float2 o1 = make_float2(O[nt][2] * inv1, O[nt][3] * inv1);
        *(float2*)(ob0 + d)          = xv0;
        *(float2*)(ob0 + DD + d)     = o0;
        *(float2*)(ob0 + 2 * DD + d) = make_float2(xv0.x * o0.x, xv0.y * o0.y);
        *(float2*)(ob1 + d)          = xv1;
        *(float2*)(ob1 + DD + d)     = o1;
        *(float2*)(ob1 + 2 * DD + d) = make_float2(xv1.x * o1.x, xv1.y * o1.y);
    }
    #undef ITER
    #undef SBURST
    #undef PVBURST
}

// ---------------------------------------------------------------------------
// c01: per-batch softmax stats (redundant per block) + partial output_two
// ---------------------------------------------------------------------------
__global__ void c01_kernel(const float* __restrict__ inp) {
    int b = blockIdx.y, sblk = blockIdx.x, tid = threadIdx.x;
    __shared__ float red[256];
    __shared__ float ws[64];

    const float* rm = g_rowmax + b * LL;
    float m = -INFINITY;
    #pragma unroll
    for (int j = 0; j < 8; j++) m = fmaxf(m, rm[tid + j * 256]);
    red[tid] = m; __syncthreads();
    for (int s = 128; s; s >>= 1) { if (tid < s) red[tid] = fmaxf(red[tid], red[tid + s]); __syncthreads(); }
    float gmax = red[0]; __syncthreads();
    float z = 0.f;
    #pragma unroll
    for (int j = 0; j < 8; j++) z += fast_exp(rm[tid + j * 256] - gmax);
    red[tid] = z; __syncthreads();
    for (int s = 128; s; s >>= 1) { if (tid < s) red[tid] += red[tid + s]; __syncthreads(); }
    float invZ = 1.0f / red[0];
    __syncthreads();

    int l0 = sblk * 64;
    if (tid < 64)
        ws[tid] = fast_exp(rm[l0 + tid] - gmax) * invZ;
    __syncthreads();
    float acc = 0.f;
    const float* xp = inp + ((size_t)b * LL + l0) * DD + tid;
    #pragma unroll 4
    for (int l = 0; l < 64; l++) acc = fmaf(ws[l], xp[(size_t)l * DD], acc);
    g_o2part[(b * 32 + sblk) * DD + tid] = acc;
}

__global__ void c2_kernel(float* __restrict__ out) {
    int b = blockIdx.y, tid = threadIdx.x;
    __shared__ float o2s[256];
    float a = 0.f;
    #pragma unroll
    for (int s = 0; s < 32; s++) a += g_o2part[(b * 32 + s) * DD + tid];
    o2s[tid] = a; __syncthreads();
    int lbase = blockIdx.x * 16;
    for (int rr = 0; rr < 16; rr++) {
        size_t ob = ((size_t)(b * LL + lbase + rr)) * OD;
        out[ob + 3 * DD + tid] = o2s[tid] * out[ob + DD + tid];
    }
}

// ---------------------------------------------------------------------------
extern "C" void kernel_launch(void* const* d_in, const int* in_sizes, int n_in,
                              void* d_out, int out_size) {
    const float* inp  = (const float*)d_in[0];
    const float* mem  = (const float*)d_in[1];
    const float* mask = (const float*)d_in[2];
    const float* wi   = (const float*)d_in[3];
    const float* wm   = (const float*)d_in[4];
    const float* ds   = (const float*)d_in[5];
    float* out = (float*)d_out;

    cudaFuncSetAttribute(fused_kernel, cudaFuncAttributeMaxDynamicSharedMemorySize, FUSED_SMEM);

    prep_kernel<<<(BB * (LL + MM)) / 8, 256>>>(inp, mem, mask, wi, wm, ds);
    fused_kernel<<<dim3(LL / LT, BB), 256, FUSED_SMEM>>>(inp, out);
    c01_kernel<<<dim3(LL / 64, BB), 256>>>(inp);
    c2_kernel<<<dim3(LL / 16, BB), 256>>>(out);
}